// round 6
// baseline (speedup 1.0000x reference)
#include <cuda_runtime.h>
#include <cuda_bf16.h>
#include <cstdint>

#define S_LEN   2048
#define BATCH   2
#define DMODEL  1024
#define NHEADS  16
#define DK      64
#define MTOT    (BATCH * S_LEN)   // 4096

// ---------------- scratch (static device globals; no dynamic allocation) ----
__device__ __nv_bfloat16 g_whi[4][DMODEL * DMODEL];   // Wq,Wk,Wv,Wo hi
__device__ __nv_bfloat16 g_wlo[4][DMODEL * DMODEL];
__device__ __nv_bfloat16 g_xhi[3][MTOT * DMODEL];     // query,key,value hi
__device__ __nv_bfloat16 g_xlo[3][MTOT * DMODEL];
__device__ __nv_bfloat16 g_phi[3][MTOT * DMODEL];     // Q,K,V head-major hi
__device__ __nv_bfloat16 g_plo[3][MTOT * DMODEL];
__device__ __nv_bfloat16 g_chi[MTOT * DMODEL];        // ctx hi (b,s,h*d)
__device__ __nv_bfloat16 g_clo[MTOT * DMODEL];

// ======================= PTX helpers =======================================
__device__ __forceinline__ uint32_t smem_u32(const void* p) {
    uint32_t a;
    asm("{ .reg .u64 t; cvta.to.shared.u64 t, %1; cvt.u32.u64 %0, t; }"
        : "=r"(a) : "l"(p));
    return a;
}

#define LDSM_X4(r0, r1, r2, r3, addr) \
    asm volatile("ldmatrix.sync.aligned.m8n8.x4.shared.b16 {%0,%1,%2,%3}, [%4];" \
                 : "=r"(r0), "=r"(r1), "=r"(r2), "=r"(r3) : "r"(addr))

#define LDSM_X4_T(r0, r1, r2, r3, addr) \
    asm volatile("ldmatrix.sync.aligned.m8n8.x4.trans.shared.b16 {%0,%1,%2,%3}, [%4];" \
                 : "=r"(r0), "=r"(r1), "=r"(r2), "=r"(r3) : "r"(addr))

#define MMA_BF16(d, a, b0, b1) \
    asm volatile("mma.sync.aligned.m16n8k16.row.col.f32.bf16.bf16.f32 " \
                 "{%0,%1,%2,%3}, {%4,%5,%6,%7}, {%8,%9}, {%0,%1,%2,%3};" \
                 : "+f"((d)[0]), "+f"((d)[1]), "+f"((d)[2]), "+f"((d)[3]) \
                 : "r"((a)[0]), "r"((a)[1]), "r"((a)[2]), "r"((a)[3]), \
                   "r"(b0), "r"(b1))

#define CP16(saddr, gptr) \
    asm volatile("cp.async.cg.shared.global [%0], [%1], 16;" \
                 :: "r"(saddr), "l"(gptr))
#define CP_COMMIT() asm volatile("cp.async.commit_group;" ::: "memory")
#define CP_WAIT1()  asm volatile("cp.async.wait_group 1;" ::: "memory")
#define CP_WAIT0()  asm volatile("cp.async.wait_group 0;" ::: "memory")

__device__ __forceinline__ void split_f4(float4 v, uint2& hi, uint2& lo) {
    uint32_t hA, hB, lA, lB;
    asm("cvt.rn.bf16x2.f32 %0, %1, %2;" : "=r"(hA) : "f"(v.y), "f"(v.x));
    asm("cvt.rn.bf16x2.f32 %0, %1, %2;" : "=r"(hB) : "f"(v.w), "f"(v.z));
    float f0 = __uint_as_float(hA << 16), f1 = __uint_as_float(hA & 0xFFFF0000u);
    float f2 = __uint_as_float(hB << 16), f3 = __uint_as_float(hB & 0xFFFF0000u);
    asm("cvt.rn.bf16x2.f32 %0, %1, %2;" : "=r"(lA) : "f"(v.y - f1), "f"(v.x - f0));
    asm("cvt.rn.bf16x2.f32 %0, %1, %2;" : "=r"(lB) : "f"(v.w - f3), "f"(v.z - f2));
    hi = make_uint2(hA, hB);
    lo = make_uint2(lA, lB);
}

__device__ __forceinline__ void split2(float a, float b, uint32_t& hi, uint32_t& lo) {
    asm("cvt.rn.bf16x2.f32 %0, %1, %2;" : "=r"(hi) : "f"(b), "f"(a));
    float fa = __uint_as_float(hi << 16), fb = __uint_as_float(hi & 0xFFFF0000u);
    asm("cvt.rn.bf16x2.f32 %0, %1, %2;" : "=r"(lo) : "f"(b - fb), "f"(a - fa));
}

// ======================= prep: fp32 -> bf16 hi/lo ==========================
__global__ void __launch_bounds__(256) split_prep(
    const float4* __restrict__ in, uint2* __restrict__ hi,
    uint2* __restrict__ lo, int n4)
{
    int i = blockIdx.x * 256 + threadIdx.x;
    if (i < n4) {
        uint2 h, l;
        split_f4(in[i], h, l);
        hi[i] = h;
        lo[i] = l;
    }
}

// ======================= HMMA split-bf16 GEMM (cp.async) ===================
// C[4096,1024] = A @ W^T + bias. Inputs pre-split bf16 hi/lo row-major.
// MODE 0: fp32 row-major out.  MODE 1: split bf16 head-major out, *scale.
#define PITCH_B   48
#define SL_SZ     6144
#define AH_OFF    0
#define AL_OFF    12288
#define WH_OFF    24576
#define WL_OFF    36864
#define BUF_SZ    49152
#define GEMM_SMEM (2 * BUF_SZ)

template <int MODE>
__global__ void __launch_bounds__(256, 2) gemm_bf16(
    const __nv_bfloat16* __restrict__ Ahi, const __nv_bfloat16* __restrict__ Alo,
    const __nv_bfloat16* __restrict__ Whi, const __nv_bfloat16* __restrict__ Wlo,
    const float* __restrict__ bias, float* __restrict__ C,
    __nv_bfloat16* __restrict__ Ohi, __nv_bfloat16* __restrict__ Olo,
    float scale)
{
    extern __shared__ __align__(128) char smem[];
    const uint32_t sb = smem_u32(smem);
    const int tid  = threadIdx.x;
    const int lane = tid & 31;
    const int wid  = tid >> 5;
    const int wm   = wid >> 2;
    const int wn   = wid & 3;
    const int m0   = blockIdx.y * 128;
    const int n0   = blockIdx.x * 128;

    const uint32_t laneOff = (uint32_t)((lane & 15) * PITCH_B + (lane >> 4) * 16);

    float acc[4][4][4];
#pragma unroll
    for (int i = 0; i < 4; ++i)
#pragma unroll
        for (int j = 0; j < 4; ++j)
#pragma unroll
            for (int r = 0; r < 4; ++r) acc[i][j][r] = 0.0f;

    // stage loads: slot = row(128) x k8(4 chunks of 8 bf16)
    auto issue = [&](int ch) {
        const int kt = ch * 32;
        const uint32_t sbuf = sb + (uint32_t)((ch & 1) * BUF_SZ);
#pragma unroll
        for (int i = 0; i < 2; ++i) {
            int slot = i * 256 + tid;
            int row  = slot >> 2;
            int k8   = slot & 3;
            uint32_t soff = (uint32_t)((k8 >> 1) * SL_SZ + row * PITCH_B + (k8 & 1) * 16);
            size_t aoff = (size_t)(m0 + row) * DMODEL + kt + k8 * 8;
            size_t woff = (size_t)(n0 + row) * DMODEL + kt + k8 * 8;
            CP16(sbuf + AH_OFF + soff, Ahi + aoff);
            CP16(sbuf + AL_OFF + soff, Alo + aoff);
            CP16(sbuf + WH_OFF + soff, Whi + woff);
            CP16(sbuf + WL_OFF + soff, Wlo + woff);
        }
        CP_COMMIT();
    };

    issue(0);
#pragma unroll 1
    for (int ch = 0; ch < 32; ++ch) {
        if (ch + 1 < 32) { issue(ch + 1); CP_WAIT1(); }
        else             { CP_WAIT0(); }
        __syncthreads();

        const uint32_t bufb = sb + (uint32_t)((ch & 1) * BUF_SZ);
        const uint32_t aBase = bufb + (uint32_t)(wm * 64) * PITCH_B + laneOff;
        const uint32_t wBase = bufb + (uint32_t)(wn * 32) * PITCH_B + laneOff;

#pragma unroll
        for (int ks = 0; ks < 2; ++ks) {
            const uint32_t so = (uint32_t)ks * SL_SZ;
            uint32_t ah[4][4], wh[2][4], tmp[2][4];
#pragma unroll
            for (int mt = 0; mt < 4; ++mt)
                LDSM_X4(ah[mt][0], ah[mt][1], ah[mt][2], ah[mt][3],
                        aBase + AH_OFF + so + mt * 16 * PITCH_B);
#pragma unroll
            for (int n2 = 0; n2 < 2; ++n2)
                LDSM_X4(wh[n2][0], wh[n2][1], wh[n2][2], wh[n2][3],
                        wBase + WH_OFF + so + n2 * 16 * PITCH_B);
#pragma unroll
            for (int mt = 0; mt < 4; ++mt)
#pragma unroll
                for (int nt = 0; nt < 4; ++nt)
                    MMA_BF16(acc[mt][nt], ah[mt],
                             wh[nt >> 1][nt & 1], wh[nt >> 1][(nt & 1) + 2]);
#pragma unroll
            for (int n2 = 0; n2 < 2; ++n2)
                LDSM_X4(tmp[n2][0], tmp[n2][1], tmp[n2][2], tmp[n2][3],
                        wBase + WL_OFF + so + n2 * 16 * PITCH_B);
#pragma unroll
            for (int mt = 0; mt < 4; ++mt)
#pragma unroll
                for (int nt = 0; nt < 4; ++nt)
                    MMA_BF16(acc[mt][nt], ah[mt],
                             tmp[nt >> 1][nt & 1], tmp[nt >> 1][(nt & 1) + 2]);
#pragma unroll
            for (int mt = 0; mt < 4; ++mt) {
                uint32_t al[4];
                LDSM_X4(al[0], al[1], al[2], al[3],
                        aBase + AL_OFF + so + mt * 16 * PITCH_B);
#pragma unroll
                for (int nt = 0; nt < 4; ++nt)
                    MMA_BF16(acc[mt][nt], al,
                             wh[nt >> 1][nt & 1], wh[nt >> 1][(nt & 1) + 2]);
            }
        }
        __syncthreads();
    }

    // ---- epilogue ----
    const int group = lane >> 2;
    const int tcol  = (lane & 3) * 2;
#pragma unroll
    for (int mt = 0; mt < 4; ++mt) {
#pragma unroll
        for (int nt = 0; nt < 4; ++nt) {
            int row = m0 + wm * 64 + mt * 16 + group;
            int col = n0 + wn * 32 + nt * 8 + tcol;
            float bx = bias[col], by = bias[col + 1];
            float v00 = acc[mt][nt][0] + bx, v01 = acc[mt][nt][1] + by;
            float v10 = acc[mt][nt][2] + bx, v11 = acc[mt][nt][3] + by;
            if (MODE == 0) {
                *(float2*)(C + (size_t)row * DMODEL + col) = make_float2(v00, v01);
                *(float2*)(C + (size_t)(row + 8) * DMODEL + col) = make_float2(v10, v11);
            } else {
                v00 *= scale; v01 *= scale; v10 *= scale; v11 *= scale;
                int h = col >> 6, d = col & 63;
                int b0_ = row >> 11, s0_ = row & 2047;
                int b1_ = (row + 8) >> 11, s1_ = (row + 8) & 2047;
                size_t a0 = (((size_t)(b0_ * NHEADS + h) * S_LEN + s0_) * DK) + d;
                size_t a1 = (((size_t)(b1_ * NHEADS + h) * S_LEN + s1_) * DK) + d;
                uint32_t h0, l0, h1, l1;
                split2(v00, v01, h0, l0);
                split2(v10, v11, h1, l1);
                *(uint32_t*)(Ohi + a0) = h0;
                *(uint32_t*)(Olo + a0) = l0;
                *(uint32_t*)(Ohi + a1) = h1;
                *(uint32_t*)(Olo + a1) = l1;
            }
        }
    }
}

// ======================= HMMA flash attention (pre-split inputs) ===========
#define APITCH    144
#define KHI_OFF   0
#define KLO_OFF   9216
#define VHI_OFF   18432
#define VLO_OFF   27648
#define KVBUF_SZ  36864
#define QHI_OFF   73728
#define QLO_OFF   92160
#define MASK_OFF  110592
#define ATTN_SMEM (MASK_OFF + 2 * 64 * 4)   // 111104

__global__ void __launch_bounds__(256) attn_mma(
    const __nv_bfloat16* __restrict__ Qhi, const __nv_bfloat16* __restrict__ Qlo,
    const __nv_bfloat16* __restrict__ Khi, const __nv_bfloat16* __restrict__ Klo,
    const __nv_bfloat16* __restrict__ Vhi, const __nv_bfloat16* __restrict__ Vlo,
    const int* __restrict__ mask,
    __nv_bfloat16* __restrict__ Chi, __nv_bfloat16* __restrict__ Clo)
{
    extern __shared__ __align__(128) char smem[];
    const uint32_t sb = smem_u32(smem);
    const int tid  = threadIdx.x;
    const int lane = tid & 31;
    const int wid  = tid >> 5;
    const int q0   = blockIdx.x * 128;
    const int h    = blockIdx.y;
    const int b    = blockIdx.z;
    const size_t base = (size_t)(b * NHEADS + h) * S_LEN * DK;

    const uint32_t laneOff = (uint32_t)((lane & 15) * APITCH + (lane >> 4) * 16);

    auto issue_kv = [&](int t) {
        const int k0 = t * 64;
        const uint32_t sp = sb + (uint32_t)((t & 1) * KVBUF_SZ);
#pragma unroll
        for (int i = 0; i < 2; ++i) {
            int slot = i * 256 + tid;
            int row  = slot >> 3;
            int d8   = slot & 7;
            uint32_t soff = (uint32_t)(row * APITCH + d8 * 16);
            size_t goff = base + (size_t)(k0 + row) * DK + d8 * 8;
            CP16(sp + KHI_OFF + soff, Khi + goff);
            CP16(sp + KLO_OFF + soff, Klo + goff);
            CP16(sp + VHI_OFF + soff, Vhi + goff);
            CP16(sp + VLO_OFF + soff, Vlo + goff);
        }
        CP_COMMIT();
    };

    // prologue: stage Q + first K/V tile
    {
#pragma unroll
        for (int i = 0; i < 4; ++i) {
            int slot = i * 256 + tid;
            int row  = slot >> 3;
            int d8   = slot & 7;
            uint32_t soff = (uint32_t)(row * APITCH + d8 * 16);
            size_t goff = base + (size_t)(q0 + row) * DK + d8 * 8;
            CP16(sb + QHI_OFF + soff, Qhi + goff);
            CP16(sb + QLO_OFF + soff, Qlo + goff);
        }
        issue_kv(0);   // commit covers Q + tile 0
    }

    uint32_t qh[4][4], ql[4][4];
    float o[8][4];
#pragma unroll
    for (int dt = 0; dt < 8; ++dt)
#pragma unroll
        for (int r = 0; r < 4; ++r) o[dt][r] = 0.0f;
    float mi0 = -1.0e30f, mi1 = -1.0e30f, li0 = 0.0f, li1 = 0.0f;

#pragma unroll 1
    for (int t = 0; t < 32; ++t) {
        const int buf = t & 1;
        if (t + 1 < 32) issue_kv(t + 1);
        if (tid < 64)
            ((int*)(smem + MASK_OFF))[buf * 64 + tid] = mask[b * S_LEN + t * 64 + tid];
        if (t + 1 < 32) CP_WAIT1(); else CP_WAIT0();
        __syncthreads();

        if (t == 0) {
            const uint32_t qbH = sb + QHI_OFF + (uint32_t)(wid * 16) * APITCH + laneOff;
            const uint32_t qbL = sb + QLO_OFF + (uint32_t)(wid * 16) * APITCH + laneOff;
#pragma unroll
            for (int s = 0; s < 4; ++s) {
                LDSM_X4(qh[s][0], qh[s][1], qh[s][2], qh[s][3], qbH + s * 32);
                LDSM_X4(ql[s][0], ql[s][1], ql[s][2], ql[s][3], qbL + s * 32);
            }
        }

        // ---- S = Q K^T (3-term split) ----
        float s_[8][4];
#pragma unroll
        for (int nt = 0; nt < 8; ++nt)
#pragma unroll
            for (int r = 0; r < 4; ++r) s_[nt][r] = 0.0f;

        const uint32_t kB = sb + (uint32_t)(buf * KVBUF_SZ) + laneOff;
#pragma unroll
        for (int st = 0; st < 4; ++st) {
#pragma unroll
            for (int g2 = 0; g2 < 4; ++g2) {
                uint32_t kh[4], kl[4];
                LDSM_X4(kh[0], kh[1], kh[2], kh[3],
                        kB + KHI_OFF + g2 * (16 * APITCH) + st * 32);
                LDSM_X4(kl[0], kl[1], kl[2], kl[3],
                        kB + KLO_OFF + g2 * (16 * APITCH) + st * 32);
                MMA_BF16(s_[2 * g2],     qh[st], kh[0], kh[2]);
                MMA_BF16(s_[2 * g2 + 1], qh[st], kh[1], kh[3]);
                MMA_BF16(s_[2 * g2],     qh[st], kl[0], kl[2]);
                MMA_BF16(s_[2 * g2 + 1], qh[st], kl[1], kl[3]);
                MMA_BF16(s_[2 * g2],     ql[st], kh[0], kh[2]);
                MMA_BF16(s_[2 * g2 + 1], ql[st], kh[1], kh[3]);
            }
        }

        // ---- mask ----
        const int* mbuf = (const int*)(smem + MASK_OFF) + buf * 64;
#pragma unroll
        for (int nt = 0; nt < 8; ++nt) {
            int2 mv = *(const int2*)&mbuf[nt * 8 + (lane & 3) * 2];
            if (mv.x == 0) { s_[nt][0] = -1.0e9f; s_[nt][2] = -1.0e9f; }
            if (mv.y == 0) { s_[nt][1] = -1.0e9f; s_[nt][3] = -1.0e9f; }
        }

        // ---- online softmax ----
        float mx0 = -1.0e30f, mx1 = -1.0e30f;
#pragma unroll
        for (int nt = 0; nt < 8; ++nt) {
            mx0 = fmaxf(mx0, fmaxf(s_[nt][0], s_[nt][1]));
            mx1 = fmaxf(mx1, fmaxf(s_[nt][2], s_[nt][3]));
        }
        mx0 = fmaxf(mx0, __shfl_xor_sync(0xffffffffu, mx0, 1));
        mx0 = fmaxf(mx0, __shfl_xor_sync(0xffffffffu, mx0, 2));
        mx1 = fmaxf(mx1, __shfl_xor_sync(0xffffffffu, mx1, 1));
        mx1 = fmaxf(mx1, __shfl_xor_sync(0xffffffffu, mx1, 2));
        const float mn0 = fmaxf(mi0, mx0), mn1 = fmaxf(mi1, mx1);
        const float a0 = __expf(mi0 - mn0), a1 = __expf(mi1 - mn1);
        mi0 = mn0; mi1 = mn1;

        float sum0 = 0.0f, sum1 = 0.0f;
#pragma unroll
        for (int nt = 0; nt < 8; ++nt) {
            s_[nt][0] = __expf(s_[nt][0] - mn0);
            s_[nt][1] = __expf(s_[nt][1] - mn0);
            s_[nt][2] = __expf(s_[nt][2] - mn1);
            s_[nt][3] = __expf(s_[nt][3] - mn1);
            sum0 += s_[nt][0] + s_[nt][1];
            sum1 += s_[nt][2] + s_[nt][3];
        }
        sum0 += __shfl_xor_sync(0xffffffffu, sum0, 1);
        sum0 += __shfl_xor_sync(0xffffffffu, sum0, 2);
        sum1 += __shfl_xor_sync(0xffffffffu, sum1, 1);
        sum1 += __shfl_xor_sync(0xffffffffu, sum1, 2);
        li0 = li0 * a0 + sum0;
        li1 = li1 * a1 + sum1;

#pragma unroll
        for (int dt = 0; dt < 8; ++dt) {
            o[dt][0] *= a0; o[dt][1] *= a0;
            o[dt][2] *= a1; o[dt][3] *= a1;
        }

        // ---- O += P V ----
        const uint32_t vB = sb + (uint32_t)(buf * KVBUF_SZ) + laneOff;
#pragma unroll
        for (int st = 0; st < 4; ++st) {
            uint32_t ph[4], pl[4];
            split2(s_[2 * st][0],     s_[2 * st][1],     ph[0], pl[0]);
            split2(s_[2 * st][2],     s_[2 * st][3],     ph[1], pl[1]);
            split2(s_[2 * st + 1][0], s_[2 * st + 1][1], ph[2], pl[2]);
            split2(s_[2 * st + 1][2], s_[2 * st + 1][3], ph[3], pl[3]);
#pragma unroll
            for (int j = 0; j < 4; ++j) {
                uint32_t vh[4], vl[4];
                LDSM_X4_T(vh[0], vh[1], vh[2], vh[3],
                          vB + VHI_OFF + st * (16 * APITCH) + j * 32);
                LDSM_X4_T(vl[0], vl[1], vl[2], vl[3],
                          vB + VLO_OFF + st * (16 * APITCH) + j * 32);
                MMA_BF16(o[2 * j],     ph, vh[0], vh[1]);
                MMA_BF16(o[2 * j + 1], ph, vh[2], vh[3]);
                MMA_BF16(o[2 * j],     ph, vl[0], vl[1]);
                MMA_BF16(o[2 * j + 1], ph, vl[2], vl[3]);
                MMA_BF16(o[2 * j],     pl, vh[0], vh[1]);
                MMA_BF16(o[2 * j + 1], pl, vh[2], vh[3]);
            }
        }
        __syncthreads();
    }

    // ---- epilogue: normalize, split, write ctx hi/lo (b, s, h*64+d) ----
    const int g  = lane >> 2;
    const int t2 = (lane & 3) * 2;
    const int row0 = q0 + wid * 16 + g;
    const int row1 = row0 + 8;
    const float inv0 = 1.0f / li0, inv1 = 1.0f / li1;
#pragma unroll
    for (int dt = 0; dt < 8; ++dt) {
        int col = h * DK + dt * 8 + t2;
        size_t a0 = (size_t)(b * S_LEN + row0) * DMODEL + col;
        size_t a1 = (size_t)(b * S_LEN + row1) * DMODEL + col;
        uint32_t h0, l0, h1, l1;
        split2(o[dt][0] * inv0, o[dt][1] * inv0, h0, l0);
        split2(o[dt][2] * inv1, o[dt][3] * inv1, h1, l1);
        *(uint32_t*)(Chi + a0) = h0;
        *(uint32_t*)(Clo + a0) = l0;
        *(uint32_t*)(Chi + a1) = h1;
        *(uint32_t*)(Clo + a1) = l1;
    }
}

// ---------------------------------------------------------------------------
extern "C" void kernel_launch(void* const* d_in, const int* in_sizes, int n_in,
                              void* d_out, int out_size)
{
    const float* query = (const float*)d_in[0];
    const float* key   = (const float*)d_in[1];
    const float* value = (const float*)d_in[2];
    const int*   mask  = (const int*)d_in[3];
    const float* Wq = (const float*)d_in[4];
    const float* bq = (const float*)d_in[5];
    const float* Wk = (const float*)d_in[6];
    const float* bk = (const float*)d_in[7];
    const float* Wv = (const float*)d_in[8];
    const float* bv = (const float*)d_in[9];
    const float* Wo = (const float*)d_in[10];
    const float* bo = (const float*)d_in[11];
    float* out = (float*)d_out;

    __nv_bfloat16 *whi, *wlo, *xhi, *xlo, *phi, *plo, *chi, *clo;
    cudaGetSymbolAddress((void**)&whi, g_whi);
    cudaGetSymbolAddress((void**)&wlo, g_wlo);
    cudaGetSymbolAddress((void**)&xhi, g_xhi);
    cudaGetSymbolAddress((void**)&xlo, g_xlo);
    cudaGetSymbolAddress((void**)&phi, g_phi);
    cudaGetSymbolAddress((void**)&plo, g_plo);
    cudaGetSymbolAddress((void**)&chi, g_chi);
    cudaGetSymbolAddress((void**)&clo, g_clo);

    cudaFuncSetAttribute(gemm_bf16<0>, cudaFuncAttributeMaxDynamicSharedMemorySize, GEMM_SMEM);
    cudaFuncSetAttribute(gemm_bf16<1>, cudaFuncAttributeMaxDynamicSharedMemorySize, GEMM_SMEM);
    cudaFuncSetAttribute(attn_mma, cudaFuncAttributeMaxDynamicSharedMemorySize, ATTN_SMEM);

    const int WN = DMODEL * DMODEL;   // 1M
    const int XN = MTOT * DMODEL;     // 4M
    const float* Ws[4] = {Wq, Wk, Wv, Wo};
    for (int i = 0; i < 4; ++i)
        split_prep<<<(WN / 4 + 255) / 256, 256>>>(
            (const float4*)Ws[i], (uint2*)(whi + (size_t)i * WN),
            (uint2*)(wlo + (size_t)i * WN), WN / 4);
    const float* Xs[3] = {query, key, value};
    for (int i = 0; i < 3; ++i)
        split_prep<<<(XN / 4 + 255) / 256, 256>>>(
            (const float4*)Xs[i], (uint2*)(xhi + (size_t)i * XN),
            (uint2*)(xlo + (size_t)i * XN), XN / 4);

    dim3 gg(DMODEL / 128, MTOT / 128);          // (8, 32) = 256 CTAs
    // projections: write split bf16 head-major (Q scaled by 1/8)
    gemm_bf16<1><<<gg, 256, GEMM_SMEM>>>(
        xhi, xlo, whi, wlo, bq, nullptr, phi, plo, 0.125f);
    gemm_bf16<1><<<gg, 256, GEMM_SMEM>>>(
        xhi + (size_t)XN, xlo + (size_t)XN, whi + (size_t)WN, wlo + (size_t)WN,
        bk, nullptr, phi + (size_t)XN, plo + (size_t)XN, 1.0f);
    gemm_bf16<1><<<gg, 256, GEMM_SMEM>>>(
        xhi + 2 * (size_t)XN, xlo + 2 * (size_t)XN, whi + 2 * (size_t)WN,
        wlo + 2 * (size_t)WN, bv, nullptr, phi + 2 * (size_t)XN,
        plo + 2 * (size_t)XN, 1.0f);

    dim3 ag(S_LEN / 128, NHEADS, BATCH);        // (16, 16, 2) = 512 CTAs
    attn_mma<<<ag, 256, ATTN_SMEM>>>(
        phi, plo, phi + (size_t)XN, plo + (size_t)XN,
        phi + 2 * (size_t)XN, plo + 2 * (size_t)XN, mask, chi, clo);

    gemm_bf16<0><<<gg, 256, GEMM_SMEM>>>(
        chi, clo, whi + 3 * (size_t)WN, wlo + 3 * (size_t)WN,
        bo, out, nullptr, nullptr, 1.0f);
}

// round 7
// speedup vs baseline: 1.2280x; 1.2280x over previous
#include <cuda_runtime.h>
#include <cuda_bf16.h>
#include <cstdint>

#define S_LEN   2048
#define BATCH   2
#define DMODEL  1024
#define NHEADS  16
#define DK      64
#define MTOT    (BATCH * S_LEN)   // 4096

// ---------------- scratch (static device globals; no dynamic allocation) ----
__device__ float g_Q[BATCH * NHEADS * S_LEN * DK];    // (b,h,s,d)
__device__ float g_K[BATCH * NHEADS * S_LEN * DK];
__device__ float g_V[BATCH * NHEADS * S_LEN * DK];
__device__ float g_ctx[MTOT * DMODEL];                // (b,s,h*d)

// ======================= warp-MMA helpers (portable PTX) ====================
__device__ __forceinline__ uint32_t smem_u32(const void* p) {
    uint32_t a;
    asm("{ .reg .u64 t; cvta.to.shared.u64 t, %1; cvt.u32.u64 %0, t; }"
        : "=r"(a) : "l"(p));
    return a;
}

#define LDSM_X4(r0, r1, r2, r3, addr) \
    asm volatile("ldmatrix.sync.aligned.m8n8.x4.shared.b16 {%0,%1,%2,%3}, [%4];" \
                 : "=r"(r0), "=r"(r1), "=r"(r2), "=r"(r3) : "r"(addr))

#define LDSM_X4_T(r0, r1, r2, r3, addr) \
    asm volatile("ldmatrix.sync.aligned.m8n8.x4.trans.shared.b16 {%0,%1,%2,%3}, [%4];" \
                 : "=r"(r0), "=r"(r1), "=r"(r2), "=r"(r3) : "r"(addr))

#define MMA_BF16(d, a, b0, b1) \
    asm volatile("mma.sync.aligned.m16n8k16.row.col.f32.bf16.bf16.f32 " \
                 "{%0,%1,%2,%3}, {%4,%5,%6,%7}, {%8,%9}, {%0,%1,%2,%3};" \
                 : "+f"((d)[0]), "+f"((d)[1]), "+f"((d)[2]), "+f"((d)[3]) \
                 : "r"((a)[0]), "r"((a)[1]), "r"((a)[2]), "r"((a)[3]), \
                   "r"(b0), "r"(b1))

#define MMA_FP16(d, a, b0, b1) \
    asm volatile("mma.sync.aligned.m16n8k16.row.col.f32.f16.f16.f32 " \
                 "{%0,%1,%2,%3}, {%4,%5,%6,%7}, {%8,%9}, {%0,%1,%2,%3};" \
                 : "+f"((d)[0]), "+f"((d)[1]), "+f"((d)[2]), "+f"((d)[3]) \
                 : "r"((a)[0]), "r"((a)[1]), "r"((a)[2]), "r"((a)[3]), \
                   "r"(b0), "r"(b1))

__device__ __forceinline__ void split_f4(float4 v, uint2& hi, uint2& lo) {
    uint32_t hA, hB, lA, lB;
    asm("cvt.rn.bf16x2.f32 %0, %1, %2;" : "=r"(hA) : "f"(v.y), "f"(v.x));
    asm("cvt.rn.bf16x2.f32 %0, %1, %2;" : "=r"(hB) : "f"(v.w), "f"(v.z));
    float f0 = __uint_as_float(hA << 16), f1 = __uint_as_float(hA & 0xFFFF0000u);
    float f2 = __uint_as_float(hB << 16), f3 = __uint_as_float(hB & 0xFFFF0000u);
    asm("cvt.rn.bf16x2.f32 %0, %1, %2;" : "=r"(lA) : "f"(v.y - f1), "f"(v.x - f0));
    asm("cvt.rn.bf16x2.f32 %0, %1, %2;" : "=r"(lB) : "f"(v.w - f3), "f"(v.z - f2));
    hi = make_uint2(hA, hB);
    lo = make_uint2(lA, lB);
}

__device__ __forceinline__ uint32_t pack_f16(float a, float b) {   // low = a
    uint32_t r;
    asm("cvt.rn.f16x2.f32 %0, %1, %2;" : "=r"(r) : "f"(b), "f"(a));
    return r;
}

// ======================= HMMA split-bf16 GEMM body =========================
#define PITCH_B   48
#define SL_SZ     6144
#define AH_OFF    0
#define AL_OFF    12288
#define WH_OFF    24576
#define WL_OFF    36864
#define BUF_SZ    49152
#define GEMM_SMEM (2 * BUF_SZ)

template <int MODE>
__device__ __forceinline__ void gemm_body(
    const float* __restrict__ A, const float* __restrict__ W,
    const float* __restrict__ bias, float* __restrict__ C, char* smem)
{
    const uint32_t sb = smem_u32(smem);
    const int tid  = threadIdx.x;
    const int lane = tid & 31;
    const int wid  = tid >> 5;
    const int wm   = wid >> 2;
    const int wn   = wid & 3;
    const int m0   = blockIdx.y * 128;
    const int n0   = blockIdx.x * 128;

    const uint32_t laneOff = (uint32_t)((lane & 15) * PITCH_B + (lane >> 4) * 16);

    float acc[4][4][4];
#pragma unroll
    for (int i = 0; i < 4; ++i)
#pragma unroll
        for (int j = 0; j < 4; ++j)
#pragma unroll
            for (int r = 0; r < 4; ++r) acc[i][j][r] = 0.0f;

#pragma unroll 1
    for (int ch = 0; ch < 32; ++ch) {
        const int kt = ch * 32;
        char* sp = smem + (ch & 1) * BUF_SZ;

#pragma unroll
        for (int i = 0; i < 4; ++i) {
            int slot = i * 256 + tid;
            int row  = slot >> 3;
            int q    = (slot & 7) << 2;
            int soff = (q >> 4) * SL_SZ + row * PITCH_B + (q & 15) * 2;
            uint2 hi, lo;
            split_f4(*(const float4*)(A + (size_t)(m0 + row) * DMODEL + kt + q), hi, lo);
            *(uint2*)(sp + AH_OFF + soff) = hi;
            *(uint2*)(sp + AL_OFF + soff) = lo;
            split_f4(*(const float4*)(W + (size_t)(n0 + row) * DMODEL + kt + q), hi, lo);
            *(uint2*)(sp + WH_OFF + soff) = hi;
            *(uint2*)(sp + WL_OFF + soff) = lo;
        }
        __syncthreads();

        const uint32_t bufb = sb + (uint32_t)((ch & 1) * BUF_SZ);
        const uint32_t aBase = bufb + (uint32_t)(wm * 64) * PITCH_B + laneOff;
        const uint32_t wBase = bufb + (uint32_t)(wn * 32) * PITCH_B + laneOff;

#pragma unroll
        for (int ks = 0; ks < 2; ++ks) {
            const uint32_t so = (uint32_t)ks * SL_SZ;
            uint32_t ah[4][4], wh[2][4], tmp[2][4];
#pragma unroll
            for (int mt = 0; mt < 4; ++mt)
                LDSM_X4(ah[mt][0], ah[mt][1], ah[mt][2], ah[mt][3],
                        aBase + AH_OFF + so + mt * 16 * PITCH_B);
#pragma unroll
            for (int n2 = 0; n2 < 2; ++n2)
                LDSM_X4(wh[n2][0], wh[n2][1], wh[n2][2], wh[n2][3],
                        wBase + WH_OFF + so + n2 * 16 * PITCH_B);
#pragma unroll
            for (int mt = 0; mt < 4; ++mt)
#pragma unroll
                for (int nt = 0; nt < 4; ++nt)
                    MMA_BF16(acc[mt][nt], ah[mt],
                             wh[nt >> 1][nt & 1], wh[nt >> 1][(nt & 1) + 2]);
#pragma unroll
            for (int n2 = 0; n2 < 2; ++n2)
                LDSM_X4(tmp[n2][0], tmp[n2][1], tmp[n2][2], tmp[n2][3],
                        wBase + WL_OFF + so + n2 * 16 * PITCH_B);
#pragma unroll
            for (int mt = 0; mt < 4; ++mt)
#pragma unroll
                for (int nt = 0; nt < 4; ++nt)
                    MMA_BF16(acc[mt][nt], ah[mt],
                             tmp[nt >> 1][nt & 1], tmp[nt >> 1][(nt & 1) + 2]);
#pragma unroll
            for (int mt = 0; mt < 4; ++mt) {
                uint32_t al[4];
                LDSM_X4(al[0], al[1], al[2], al[3],
                        aBase + AL_OFF + so + mt * 16 * PITCH_B);
#pragma unroll
                for (int nt = 0; nt < 4; ++nt)
                    MMA_BF16(acc[mt][nt], al,
                             wh[nt >> 1][nt & 1], wh[nt >> 1][(nt & 1) + 2]);
            }
        }
        __syncthreads();
    }

    const int group = lane >> 2;
    const int tcol  = (lane & 3) * 2;
#pragma unroll
    for (int mt = 0; mt < 4; ++mt) {
#pragma unroll
        for (int nt = 0; nt < 4; ++nt) {
            int row = m0 + wm * 64 + mt * 16 + group;
            int col = n0 + wn * 32 + nt * 8 + tcol;
            float bx = bias[col], by = bias[col + 1];
            float2 v0 = make_float2(acc[mt][nt][0] + bx, acc[mt][nt][1] + by);
            float2 v1 = make_float2(acc[mt][nt][2] + bx, acc[mt][nt][3] + by);
            if (MODE == 0) {
                *(float2*)(C + (size_t)row * DMODEL + col) = v0;
                *(float2*)(C + (size_t)(row + 8) * DMODEL + col) = v1;
            } else {
                int h = col >> 6, d = col & 63;
                int b0_ = row >> 11, s0_ = row & 2047;
                int b1_ = (row + 8) >> 11, s1_ = (row + 8) & 2047;
                *(float2*)(C + (((size_t)(b0_ * NHEADS + h) * S_LEN + s0_) * DK) + d) = v0;
                *(float2*)(C + (((size_t)(b1_ * NHEADS + h) * S_LEN + s1_) * DK) + d) = v1;
            }
        }
    }
}

// fused Q/K/V projection: blockIdx.z selects input/weight/bias/output
__global__ void __launch_bounds__(256, 2) gemm_qkv(
    const float* __restrict__ q, const float* __restrict__ k,
    const float* __restrict__ v,
    const float* __restrict__ Wq, const float* __restrict__ Wk,
    const float* __restrict__ Wv,
    const float* __restrict__ bq, const float* __restrict__ bk,
    const float* __restrict__ bv,
    float* __restrict__ Qd, float* __restrict__ Kd, float* __restrict__ Vd)
{
    extern __shared__ __align__(128) char smem[];
    const float *A, *W, *bias;
    float* C;
    if (blockIdx.z == 0)      { A = q; W = Wq; bias = bq; C = Qd; }
    else if (blockIdx.z == 1) { A = k; W = Wk; bias = bk; C = Kd; }
    else                      { A = v; W = Wv; bias = bv; C = Vd; }
    gemm_body<1>(A, W, bias, C, smem);
}

__global__ void __launch_bounds__(256, 2) gemm_out(
    const float* __restrict__ A, const float* __restrict__ W,
    const float* __restrict__ bias, float* __restrict__ C)
{
    extern __shared__ __align__(128) char smem[];
    gemm_body<0>(A, W, bias, C, smem);
}

// ======================= HMMA flash attention ==============================
// K: split bf16 hi/lo (3-term QK).  V: single fp16, P: fp16 (1-term PV).
#define APITCH    144
#define KHI_OFF   0
#define KLO_OFF   9216
#define VF_OFF    18432
#define KVBUF_SZ  27648
#define QHI_OFF   55296
#define QLO_OFF   73728
#define MASK_OFF  92160
#define ATTN_SMEM (MASK_OFF + 2 * 64 * 4)   // 92672

__global__ void __launch_bounds__(256) attn_mma(
    const float* __restrict__ Q, const float* __restrict__ K,
    const float* __restrict__ V, const int* __restrict__ mask,
    float* __restrict__ ctx)
{
    extern __shared__ __align__(128) char smem[];
    const uint32_t sb = smem_u32(smem);
    const int tid  = threadIdx.x;
    const int lane = tid & 31;
    const int wid  = tid >> 5;
    const int q0   = blockIdx.x * 128;
    const int h    = blockIdx.y;
    const int b    = blockIdx.z;
    const size_t base = (size_t)(b * NHEADS + h) * S_LEN * DK;

    const uint32_t laneOff = (uint32_t)((lane & 15) * APITCH + (lane >> 4) * 16);

    // ---- stage Q (scaled by 1/8), split hi/lo ----
#pragma unroll
    for (int i = 0; i < 8; ++i) {
        int slot = i * 256 + tid;
        int row  = slot >> 4;
        int dq   = (slot & 15) << 2;
        float4 v = *(const float4*)(Q + base + (size_t)(q0 + row) * DK + dq);
        v.x *= 0.125f; v.y *= 0.125f; v.z *= 0.125f; v.w *= 0.125f;
        uint2 hi, lo;
        split_f4(v, hi, lo);
        int soff = row * APITCH + dq * 2;
        *(uint2*)(smem + QHI_OFF + soff) = hi;
        *(uint2*)(smem + QLO_OFF + soff) = lo;
    }
    __syncthreads();

    uint32_t qh[4][4], ql[4][4];
    {
        const uint32_t qbH = sb + QHI_OFF + (uint32_t)(wid * 16) * APITCH + laneOff;
        const uint32_t qbL = sb + QLO_OFF + (uint32_t)(wid * 16) * APITCH + laneOff;
#pragma unroll
        for (int s = 0; s < 4; ++s) {
            LDSM_X4(qh[s][0], qh[s][1], qh[s][2], qh[s][3], qbH + s * 32);
            LDSM_X4(ql[s][0], ql[s][1], ql[s][2], ql[s][3], qbL + s * 32);
        }
    }

    float o[8][4];
#pragma unroll
    for (int dt = 0; dt < 8; ++dt)
#pragma unroll
        for (int r = 0; r < 4; ++r) o[dt][r] = 0.0f;
    float mi0 = -1.0e30f, mi1 = -1.0e30f, li0 = 0.0f, li1 = 0.0f;

#pragma unroll 1
    for (int t = 0; t < 32; ++t) {
        const int k0 = t * 64;
        const int buf = t & 1;
        char* sp = smem + buf * KVBUF_SZ;

        // ---- load K (split bf16) and V (fp16) ----
#pragma unroll
        for (int i = 0; i < 4; ++i) {
            int slot = i * 256 + tid;
            int row  = slot >> 4;
            int dq   = (slot & 15) << 2;
            int soff = row * APITCH + dq * 2;
            uint2 hi, lo;
            split_f4(*(const float4*)(K + base + (size_t)(k0 + row) * DK + dq), hi, lo);
            *(uint2*)(sp + KHI_OFF + soff) = hi;
            *(uint2*)(sp + KLO_OFF + soff) = lo;
            float4 vv = *(const float4*)(V + base + (size_t)(k0 + row) * DK + dq);
            *(uint2*)(sp + VF_OFF + soff) =
                make_uint2(pack_f16(vv.x, vv.y), pack_f16(vv.z, vv.w));
        }
        if (tid < 64)
            ((int*)(smem + MASK_OFF))[buf * 64 + tid] = mask[b * S_LEN + k0 + tid];
        __syncthreads();

        // ---- S = Q K^T (3-term split bf16) ----
        float s_[8][4];
#pragma unroll
        for (int nt = 0; nt < 8; ++nt)
#pragma unroll
            for (int r = 0; r < 4; ++r) s_[nt][r] = 0.0f;

        const uint32_t kB = sb + (uint32_t)(buf * KVBUF_SZ) + laneOff;
#pragma unroll
        for (int st = 0; st < 4; ++st) {
#pragma unroll
            for (int g2 = 0; g2 < 4; ++g2) {
                uint32_t kh[4], kl[4];
                LDSM_X4(kh[0], kh[1], kh[2], kh[3],
                        kB + KHI_OFF + g2 * (16 * APITCH) + st * 32);
                LDSM_X4(kl[0], kl[1], kl[2], kl[3],
                        kB + KLO_OFF + g2 * (16 * APITCH) + st * 32);
                MMA_BF16(s_[2 * g2],     qh[st], kh[0], kh[2]);
                MMA_BF16(s_[2 * g2 + 1], qh[st], kh[1], kh[3]);
                MMA_BF16(s_[2 * g2],     qh[st], kl[0], kl[2]);
                MMA_BF16(s_[2 * g2 + 1], qh[st], kl[1], kl[3]);
                MMA_BF16(s_[2 * g2],     ql[st], kh[0], kh[2]);
                MMA_BF16(s_[2 * g2 + 1], ql[st], kh[1], kh[3]);
            }
        }

        // ---- mask ----
        const int* mbuf = (const int*)(smem + MASK_OFF) + buf * 64;
#pragma unroll
        for (int nt = 0; nt < 8; ++nt) {
            int2 mv = *(const int2*)&mbuf[nt * 8 + (lane & 3) * 2];
            if (mv.x == 0) { s_[nt][0] = -1.0e9f; s_[nt][2] = -1.0e9f; }
            if (mv.y == 0) { s_[nt][1] = -1.0e9f; s_[nt][3] = -1.0e9f; }
        }

        // ---- online softmax ----
        float mx0 = -1.0e30f, mx1 = -1.0e30f;
#pragma unroll
        for (int nt = 0; nt < 8; ++nt) {
            mx0 = fmaxf(mx0, fmaxf(s_[nt][0], s_[nt][1]));
            mx1 = fmaxf(mx1, fmaxf(s_[nt][2], s_[nt][3]));
        }
        mx0 = fmaxf(mx0, __shfl_xor_sync(0xffffffffu, mx0, 1));
        mx0 = fmaxf(mx0, __shfl_xor_sync(0xffffffffu, mx0, 2));
        mx1 = fmaxf(mx1, __shfl_xor_sync(0xffffffffu, mx1, 1));
        mx1 = fmaxf(mx1, __shfl_xor_sync(0xffffffffu, mx1, 2));
        const float mn0 = fmaxf(mi0, mx0), mn1 = fmaxf(mi1, mx1);
        const float a0 = __expf(mi0 - mn0), a1 = __expf(mi1 - mn1);
        mi0 = mn0; mi1 = mn1;

        float sum0 = 0.0f, sum1 = 0.0f;
#pragma unroll
        for (int nt = 0; nt < 8; ++nt) {
            s_[nt][0] = __expf(s_[nt][0] - mn0);
            s_[nt][1] = __expf(s_[nt][1] - mn0);
            s_[nt][2] = __expf(s_[nt][2] - mn1);
            s_[nt][3] = __expf(s_[nt][3] - mn1);
            sum0 += s_[nt][0] + s_[nt][1];
            sum1 += s_[nt][2] + s_[nt][3];
        }
        sum0 += __shfl_xor_sync(0xffffffffu, sum0, 1);
        sum0 += __shfl_xor_sync(0xffffffffu, sum0, 2);
        sum1 += __shfl_xor_sync(0xffffffffu, sum1, 1);
        sum1 += __shfl_xor_sync(0xffffffffu, sum1, 2);
        li0 = li0 * a0 + sum0;
        li1 = li1 * a1 + sum1;

#pragma unroll
        for (int dt = 0; dt < 8; ++dt) {
            o[dt][0] *= a0; o[dt][1] *= a0;
            o[dt][2] *= a1; o[dt][3] *= a1;
        }

        // ---- O += P V (single-term fp16) ----
        const uint32_t vB = sb + (uint32_t)(buf * KVBUF_SZ) + laneOff;
#pragma unroll
        for (int st = 0; st < 4; ++st) {
            uint32_t pf[4];
            pf[0] = pack_f16(s_[2 * st][0],     s_[2 * st][1]);
            pf[1] = pack_f16(s_[2 * st][2],     s_[2 * st][3]);
            pf[2] = pack_f16(s_[2 * st + 1][0], s_[2 * st + 1][1]);
            pf[3] = pack_f16(s_[2 * st + 1][2], s_[2 * st + 1][3]);
#pragma unroll
            for (int j = 0; j < 4; ++j) {
                uint32_t vf[4];
                LDSM_X4_T(vf[0], vf[1], vf[2], vf[3],
                          vB + VF_OFF + st * (16 * APITCH) + j * 32);
                MMA_FP16(o[2 * j],     pf, vf[0], vf[1]);
                MMA_FP16(o[2 * j + 1], pf, vf[2], vf[3]);
            }
        }
        __syncthreads();
    }

    // ---- epilogue: normalize, write ctx (b, s, h*64+d) ----
    const int g  = lane >> 2;
    const int t2 = (lane & 3) * 2;
    const int row0 = q0 + wid * 16 + g;
    const int row1 = row0 + 8;
    const float inv0 = 1.0f / li0, inv1 = 1.0f / li1;
#pragma unroll
    for (int dt = 0; dt < 8; ++dt) {
        int col = h * DK + dt * 8 + t2;
        *(float2*)(ctx + (size_t)(b * S_LEN + row0) * DMODEL + col) =
            make_float2(o[dt][0] * inv0, o[dt][1] * inv0);
        *(float2*)(ctx + (size_t)(b * S_LEN + row1) * DMODEL + col) =
            make_float2(o[dt][2] * inv1, o[dt][3] * inv1);
    }
}

// ---------------------------------------------------------------------------
extern "C" void kernel_launch(void* const* d_in, const int* in_sizes, int n_in,
                              void* d_out, int out_size)
{
    const float* query = (const float*)d_in[0];
    const float* key   = (const float*)d_in[1];
    const float* value = (const float*)d_in[2];
    const int*   mask  = (const int*)d_in[3];
    const float* Wq = (const float*)d_in[4];
    const float* bq = (const float*)d_in[5];
    const float* Wk = (const float*)d_in[6];
    const float* bk = (const float*)d_in[7];
    const float* Wv = (const float*)d_in[8];
    const float* bv = (const float*)d_in[9];
    const float* Wo = (const float*)d_in[10];
    const float* bo = (const float*)d_in[11];
    float* out = (float*)d_out;

    float *Qd, *Kd, *Vd, *Cd;
    cudaGetSymbolAddress((void**)&Qd, g_Q);
    cudaGetSymbolAddress((void**)&Kd, g_K);
    cudaGetSymbolAddress((void**)&Vd, g_V);
    cudaGetSymbolAddress((void**)&Cd, g_ctx);

    cudaFuncSetAttribute(gemm_qkv, cudaFuncAttributeMaxDynamicSharedMemorySize, GEMM_SMEM);
    cudaFuncSetAttribute(gemm_out, cudaFuncAttributeMaxDynamicSharedMemorySize, GEMM_SMEM);
    cudaFuncSetAttribute(attn_mma, cudaFuncAttributeMaxDynamicSharedMemorySize, ATTN_SMEM);

    dim3 gq(DMODEL / 128, MTOT / 128, 3);       // (8, 32, 3) = 768 CTAs
    gemm_qkv<<<gq, 256, GEMM_SMEM>>>(query, key, value, Wq, Wk, Wv,
                                     bq, bk, bv, Qd, Kd, Vd);

    dim3 ag(S_LEN / 128, NHEADS, BATCH);        // (16, 16, 2) = 512 CTAs
    attn_mma<<<ag, 256, ATTN_SMEM>>>(Qd, Kd, Vd, mask, Cd);

    dim3 gg(DMODEL / 128, MTOT / 128);          // (8, 32) = 256 CTAs
    gemm_out<<<gg, 256, GEMM_SMEM>>>(Cd, Wo, bo, out);
}

// round 8
// speedup vs baseline: 1.2691x; 1.0334x over previous
#include <cuda_runtime.h>
#include <cuda_bf16.h>
#include <cstdint>

#define S_LEN   2048
#define BATCH   2
#define DMODEL  1024
#define NHEADS  16
#define DK      64
#define MTOT    (BATCH * S_LEN)   // 4096

// ---------------- scratch (static device globals; no dynamic allocation) ----
__device__ float g_Q[BATCH * NHEADS * S_LEN * DK];    // (b,h,s,d)
__device__ float g_K[BATCH * NHEADS * S_LEN * DK];
__device__ float g_V[BATCH * NHEADS * S_LEN * DK];
__device__ float g_ctx[MTOT * DMODEL];                // (b,s,h*d)

// ======================= warp-MMA helpers (portable PTX) ====================
__device__ __forceinline__ uint32_t smem_u32(const void* p) {
    uint32_t a;
    asm("{ .reg .u64 t; cvta.to.shared.u64 t, %1; cvt.u32.u64 %0, t; }"
        : "=r"(a) : "l"(p));
    return a;
}

#define LDSM_X4(r0, r1, r2, r3, addr) \
    asm volatile("ldmatrix.sync.aligned.m8n8.x4.shared.b16 {%0,%1,%2,%3}, [%4];" \
                 : "=r"(r0), "=r"(r1), "=r"(r2), "=r"(r3) : "r"(addr))

#define LDSM_X4_T(r0, r1, r2, r3, addr) \
    asm volatile("ldmatrix.sync.aligned.m8n8.x4.trans.shared.b16 {%0,%1,%2,%3}, [%4];" \
                 : "=r"(r0), "=r"(r1), "=r"(r2), "=r"(r3) : "r"(addr))

#define MMA_BF16(d, a, b0, b1) \
    asm volatile("mma.sync.aligned.m16n8k16.row.col.f32.bf16.bf16.f32 " \
                 "{%0,%1,%2,%3}, {%4,%5,%6,%7}, {%8,%9}, {%0,%1,%2,%3};" \
                 : "+f"((d)[0]), "+f"((d)[1]), "+f"((d)[2]), "+f"((d)[3]) \
                 : "r"((a)[0]), "r"((a)[1]), "r"((a)[2]), "r"((a)[3]), \
                   "r"(b0), "r"(b1))

#define MMA_FP16(d, a, b0, b1) \
    asm volatile("mma.sync.aligned.m16n8k16.row.col.f32.f16.f16.f32 " \
                 "{%0,%1,%2,%3}, {%4,%5,%6,%7}, {%8,%9}, {%0,%1,%2,%3};" \
                 : "+f"((d)[0]), "+f"((d)[1]), "+f"((d)[2]), "+f"((d)[3]) \
                 : "r"((a)[0]), "r"((a)[1]), "r"((a)[2]), "r"((a)[3]), \
                   "r"(b0), "r"(b1))

__device__ __forceinline__ void split_f4(float4 v, uint2& hi, uint2& lo) {
    uint32_t hA, hB, lA, lB;
    asm("cvt.rn.bf16x2.f32 %0, %1, %2;" : "=r"(hA) : "f"(v.y), "f"(v.x));
    asm("cvt.rn.bf16x2.f32 %0, %1, %2;" : "=r"(hB) : "f"(v.w), "f"(v.z));
    float f0 = __uint_as_float(hA << 16), f1 = __uint_as_float(hA & 0xFFFF0000u);
    float f2 = __uint_as_float(hB << 16), f3 = __uint_as_float(hB & 0xFFFF0000u);
    asm("cvt.rn.bf16x2.f32 %0, %1, %2;" : "=r"(lA) : "f"(v.y - f1), "f"(v.x - f0));
    asm("cvt.rn.bf16x2.f32 %0, %1, %2;" : "=r"(lB) : "f"(v.w - f3), "f"(v.z - f2));
    hi = make_uint2(hA, hB);
    lo = make_uint2(lA, lB);
}

__device__ __forceinline__ uint32_t pack_f16(float a, float b) {   // low = a
    uint32_t r;
    asm("cvt.rn.f16x2.f32 %0, %1, %2;" : "=r"(r) : "f"(b), "f"(a));
    return r;
}

// ======================= HMMA split-bf16 GEMM body =========================
// Software-pipelined: register prefetch of next chunk, ONE barrier per iter.
#define PITCH_B   48
#define SL_SZ     6144
#define AH_OFF    0
#define AL_OFF    12288
#define WH_OFF    24576
#define WL_OFF    36864
#define BUF_SZ    49152
#define GEMM_SMEM (2 * BUF_SZ)

template <int MODE>
__device__ __forceinline__ void gemm_body(
    const float* __restrict__ A, const float* __restrict__ W,
    const float* __restrict__ bias, float* __restrict__ C, char* smem)
{
    const uint32_t sb = smem_u32(smem);
    const int tid  = threadIdx.x;
    const int lane = tid & 31;
    const int wid  = tid >> 5;
    const int wm   = wid >> 2;
    const int wn   = wid & 3;
    const int m0   = blockIdx.y * 128;
    const int n0   = blockIdx.x * 128;

    const uint32_t laneOff = (uint32_t)((lane & 15) * PITCH_B + (lane >> 4) * 16);

    float acc[4][4][4];
#pragma unroll
    for (int i = 0; i < 4; ++i)
#pragma unroll
        for (int j = 0; j < 4; ++j)
#pragma unroll
            for (int r = 0; r < 4; ++r) acc[i][j][r] = 0.0f;

    // prefetch registers for the incoming chunk
    float4 pa[4], pw[4];
#pragma unroll
    for (int i = 0; i < 4; ++i) {
        int slot = i * 256 + tid;
        int row  = slot >> 3;
        int q    = (slot & 7) << 2;
        pa[i] = *(const float4*)(A + (size_t)(m0 + row) * DMODEL + q);
        pw[i] = *(const float4*)(W + (size_t)(n0 + row) * DMODEL + q);
    }

#pragma unroll 1
    for (int ch = 0; ch < 32; ++ch) {
        char* sp = smem + (ch & 1) * BUF_SZ;

        // ---- store prefetched chunk (split bf16) to smem ----
#pragma unroll
        for (int i = 0; i < 4; ++i) {
            int slot = i * 256 + tid;
            int row  = slot >> 3;
            int q    = (slot & 7) << 2;
            int soff = (q >> 4) * SL_SZ + row * PITCH_B + (q & 15) * 2;
            uint2 hi, lo;
            split_f4(pa[i], hi, lo);
            *(uint2*)(sp + AH_OFF + soff) = hi;
            *(uint2*)(sp + AL_OFF + soff) = lo;
            split_f4(pw[i], hi, lo);
            *(uint2*)(sp + WH_OFF + soff) = hi;
            *(uint2*)(sp + WL_OFF + soff) = lo;
        }
        __syncthreads();

        // ---- issue loads for next chunk (latency hidden by MMAs below) ----
        if (ch + 1 < 32) {
            const int kt = (ch + 1) * 32;
#pragma unroll
            for (int i = 0; i < 4; ++i) {
                int slot = i * 256 + tid;
                int row  = slot >> 3;
                int q    = (slot & 7) << 2;
                pa[i] = *(const float4*)(A + (size_t)(m0 + row) * DMODEL + kt + q);
                pw[i] = *(const float4*)(W + (size_t)(n0 + row) * DMODEL + kt + q);
            }
        }

        const uint32_t bufb = sb + (uint32_t)((ch & 1) * BUF_SZ);
        const uint32_t aBase = bufb + (uint32_t)(wm * 64) * PITCH_B + laneOff;
        const uint32_t wBase = bufb + (uint32_t)(wn * 32) * PITCH_B + laneOff;

#pragma unroll
        for (int ks = 0; ks < 2; ++ks) {
            const uint32_t so = (uint32_t)ks * SL_SZ;
            uint32_t ah[4][4], wh[2][4], tmp[2][4];
#pragma unroll
            for (int mt = 0; mt < 4; ++mt)
                LDSM_X4(ah[mt][0], ah[mt][1], ah[mt][2], ah[mt][3],
                        aBase + AH_OFF + so + mt * 16 * PITCH_B);
#pragma unroll
            for (int n2 = 0; n2 < 2; ++n2)
                LDSM_X4(wh[n2][0], wh[n2][1], wh[n2][2], wh[n2][3],
                        wBase + WH_OFF + so + n2 * 16 * PITCH_B);
#pragma unroll
            for (int mt = 0; mt < 4; ++mt)
#pragma unroll
                for (int nt = 0; nt < 4; ++nt)
                    MMA_BF16(acc[mt][nt], ah[mt],
                             wh[nt >> 1][nt & 1], wh[nt >> 1][(nt & 1) + 2]);
#pragma unroll
            for (int n2 = 0; n2 < 2; ++n2)
                LDSM_X4(tmp[n2][0], tmp[n2][1], tmp[n2][2], tmp[n2][3],
                        wBase + WL_OFF + so + n2 * 16 * PITCH_B);
#pragma unroll
            for (int mt = 0; mt < 4; ++mt)
#pragma unroll
                for (int nt = 0; nt < 4; ++nt)
                    MMA_BF16(acc[mt][nt], ah[mt],
                             tmp[nt >> 1][nt & 1], tmp[nt >> 1][(nt & 1) + 2]);
#pragma unroll
            for (int mt = 0; mt < 4; ++mt) {
                uint32_t al[4];
                LDSM_X4(al[0], al[1], al[2], al[3],
                        aBase + AL_OFF + so + mt * 16 * PITCH_B);
#pragma unroll
                for (int nt = 0; nt < 4; ++nt)
                    MMA_BF16(acc[mt][nt], al,
                             wh[nt >> 1][nt & 1], wh[nt >> 1][(nt & 1) + 2]);
            }
        }
        // no second barrier: next iter stores to the OTHER buffer; a warp
        // can't return to THIS buffer without passing the next barrier.
    }

    const int group = lane >> 2;
    const int tcol  = (lane & 3) * 2;
#pragma unroll
    for (int mt = 0; mt < 4; ++mt) {
#pragma unroll
        for (int nt = 0; nt < 4; ++nt) {
            int row = m0 + wm * 64 + mt * 16 + group;
            int col = n0 + wn * 32 + nt * 8 + tcol;
            float bx = bias[col], by = bias[col + 1];
            float2 v0 = make_float2(acc[mt][nt][0] + bx, acc[mt][nt][1] + by);
            float2 v1 = make_float2(acc[mt][nt][2] + bx, acc[mt][nt][3] + by);
            if (MODE == 0) {
                *(float2*)(C + (size_t)row * DMODEL + col) = v0;
                *(float2*)(C + (size_t)(row + 8) * DMODEL + col) = v1;
            } else {
                int h = col >> 6, d = col & 63;
                int b0_ = row >> 11, s0_ = row & 2047;
                int b1_ = (row + 8) >> 11, s1_ = (row + 8) & 2047;
                *(float2*)(C + (((size_t)(b0_ * NHEADS + h) * S_LEN + s0_) * DK) + d) = v0;
                *(float2*)(C + (((size_t)(b1_ * NHEADS + h) * S_LEN + s1_) * DK) + d) = v1;
            }
        }
    }
}

// fused Q/K/V projection: blockIdx.z selects input/weight/bias/output
__global__ void __launch_bounds__(256, 2) gemm_qkv(
    const float* __restrict__ q, const float* __restrict__ k,
    const float* __restrict__ v,
    const float* __restrict__ Wq, const float* __restrict__ Wk,
    const float* __restrict__ Wv,
    const float* __restrict__ bq, const float* __restrict__ bk,
    const float* __restrict__ bv,
    float* __restrict__ Qd, float* __restrict__ Kd, float* __restrict__ Vd)
{
    extern __shared__ __align__(128) char smem[];
    const float *A, *W, *bias;
    float* C;
    if (blockIdx.z == 0)      { A = q; W = Wq; bias = bq; C = Qd; }
    else if (blockIdx.z == 1) { A = k; W = Wk; bias = bk; C = Kd; }
    else                      { A = v; W = Wv; bias = bv; C = Vd; }
    gemm_body<1>(A, W, bias, C, smem);
}

__global__ void __launch_bounds__(256, 2) gemm_out(
    const float* __restrict__ A, const float* __restrict__ W,
    const float* __restrict__ bias, float* __restrict__ C)
{
    extern __shared__ __align__(128) char smem[];
    gemm_body<0>(A, W, bias, C, smem);
}

// ======================= HMMA flash attention ==============================
// K: split bf16 hi/lo (3-term QK).  V: single fp16, P: fp16 (1-term PV).
// Software-pipelined K/V register prefetch, ONE barrier per k-tile.
#define APITCH    144
#define KHI_OFF   0
#define KLO_OFF   9216
#define VF_OFF    18432
#define KVBUF_SZ  27648
#define QHI_OFF   55296
#define QLO_OFF   73728
#define MASK_OFF  92160
#define ATTN_SMEM (MASK_OFF + 2 * 64 * 4)   // 92672

__global__ void __launch_bounds__(256, 2) attn_mma(
    const float* __restrict__ Q, const float* __restrict__ K,
    const float* __restrict__ V, const int* __restrict__ mask,
    float* __restrict__ ctx)
{
    extern __shared__ __align__(128) char smem[];
    const uint32_t sb = smem_u32(smem);
    const int tid  = threadIdx.x;
    const int lane = tid & 31;
    const int wid  = tid >> 5;
    const int q0   = blockIdx.x * 128;
    const int h    = blockIdx.y;
    const int b    = blockIdx.z;
    const size_t base = (size_t)(b * NHEADS + h) * S_LEN * DK;

    const uint32_t laneOff = (uint32_t)((lane & 15) * APITCH + (lane >> 4) * 16);

    // ---- stage Q (scaled by 1/8), split hi/lo ----
#pragma unroll
    for (int i = 0; i < 8; ++i) {
        int slot = i * 256 + tid;
        int row  = slot >> 4;
        int dq   = (slot & 15) << 2;
        float4 v = *(const float4*)(Q + base + (size_t)(q0 + row) * DK + dq);
        v.x *= 0.125f; v.y *= 0.125f; v.z *= 0.125f; v.w *= 0.125f;
        uint2 hi, lo;
        split_f4(v, hi, lo);
        int soff = row * APITCH + dq * 2;
        *(uint2*)(smem + QHI_OFF + soff) = hi;
        *(uint2*)(smem + QLO_OFF + soff) = lo;
    }

    // prefetch K/V tile 0 into registers (in flight across the barrier)
    float4 pk[4], pv[4];
#pragma unroll
    for (int i = 0; i < 4; ++i) {
        int slot = i * 256 + tid;
        int row  = slot >> 4;
        int dq   = (slot & 15) << 2;
        size_t goff = base + (size_t)row * DK + dq;
        pk[i] = *(const float4*)(K + goff);
        pv[i] = *(const float4*)(V + goff);
    }
    __syncthreads();

    uint32_t qh[4][4], ql[4][4];
    {
        const uint32_t qbH = sb + QHI_OFF + (uint32_t)(wid * 16) * APITCH + laneOff;
        const uint32_t qbL = sb + QLO_OFF + (uint32_t)(wid * 16) * APITCH + laneOff;
#pragma unroll
        for (int s = 0; s < 4; ++s) {
            LDSM_X4(qh[s][0], qh[s][1], qh[s][2], qh[s][3], qbH + s * 32);
            LDSM_X4(ql[s][0], ql[s][1], ql[s][2], ql[s][3], qbL + s * 32);
        }
    }

    float o[8][4];
#pragma unroll
    for (int dt = 0; dt < 8; ++dt)
#pragma unroll
        for (int r = 0; r < 4; ++r) o[dt][r] = 0.0f;
    float mi0 = -1.0e30f, mi1 = -1.0e30f, li0 = 0.0f, li1 = 0.0f;

#pragma unroll 1
    for (int t = 0; t < 32; ++t) {
        const int buf = t & 1;
        char* sp = smem + buf * KVBUF_SZ;

        // ---- store prefetched K (split bf16) and V (fp16) to smem ----
#pragma unroll
        for (int i = 0; i < 4; ++i) {
            int slot = i * 256 + tid;
            int row  = slot >> 4;
            int dq   = (slot & 15) << 2;
            int soff = row * APITCH + dq * 2;
            uint2 hi, lo;
            split_f4(pk[i], hi, lo);
            *(uint2*)(sp + KHI_OFF + soff) = hi;
            *(uint2*)(sp + KLO_OFF + soff) = lo;
            *(uint2*)(sp + VF_OFF + soff) =
                make_uint2(pack_f16(pv[i].x, pv[i].y), pack_f16(pv[i].z, pv[i].w));
        }
        if (tid < 64)
            ((int*)(smem + MASK_OFF))[buf * 64 + tid] = mask[b * S_LEN + t * 64 + tid];
        __syncthreads();

        // ---- issue K/V loads for next tile (hidden under MMAs) ----
        if (t + 1 < 32) {
            const int k1 = (t + 1) * 64;
#pragma unroll
            for (int i = 0; i < 4; ++i) {
                int slot = i * 256 + tid;
                int row  = slot >> 4;
                int dq   = (slot & 15) << 2;
                size_t goff = base + (size_t)(k1 + row) * DK + dq;
                pk[i] = *(const float4*)(K + goff);
                pv[i] = *(const float4*)(V + goff);
            }
        }

        // ---- S = Q K^T (3-term split bf16) ----
        float s_[8][4];
#pragma unroll
        for (int nt = 0; nt < 8; ++nt)
#pragma unroll
            for (int r = 0; r < 4; ++r) s_[nt][r] = 0.0f;

        const uint32_t kB = sb + (uint32_t)(buf * KVBUF_SZ) + laneOff;
#pragma unroll
        for (int st = 0; st < 4; ++st) {
#pragma unroll
            for (int g2 = 0; g2 < 4; ++g2) {
                uint32_t kh[4], kl[4];
                LDSM_X4(kh[0], kh[1], kh[2], kh[3],
                        kB + KHI_OFF + g2 * (16 * APITCH) + st * 32);
                LDSM_X4(kl[0], kl[1], kl[2], kl[3],
                        kB + KLO_OFF + g2 * (16 * APITCH) + st * 32);
                MMA_BF16(s_[2 * g2],     qh[st], kh[0], kh[2]);
                MMA_BF16(s_[2 * g2 + 1], qh[st], kh[1], kh[3]);
                MMA_BF16(s_[2 * g2],     qh[st], kl[0], kl[2]);
                MMA_BF16(s_[2 * g2 + 1], qh[st], kl[1], kl[3]);
                MMA_BF16(s_[2 * g2],     ql[st], kh[0], kh[2]);
                MMA_BF16(s_[2 * g2 + 1], ql[st], kh[1], kh[3]);
            }
        }

        // ---- mask ----
        const int* mbuf = (const int*)(smem + MASK_OFF) + buf * 64;
#pragma unroll
        for (int nt = 0; nt < 8; ++nt) {
            int2 mv = *(const int2*)&mbuf[nt * 8 + (lane & 3) * 2];
            if (mv.x == 0) { s_[nt][0] = -1.0e9f; s_[nt][2] = -1.0e9f; }
            if (mv.y == 0) { s_[nt][1] = -1.0e9f; s_[nt][3] = -1.0e9f; }
        }

        // ---- online softmax ----
        float mx0 = -1.0e30f, mx1 = -1.0e30f;
#pragma unroll
        for (int nt = 0; nt < 8; ++nt) {
            mx0 = fmaxf(mx0, fmaxf(s_[nt][0], s_[nt][1]));
            mx1 = fmaxf(mx1, fmaxf(s_[nt][2], s_[nt][3]));
        }
        mx0 = fmaxf(mx0, __shfl_xor_sync(0xffffffffu, mx0, 1));
        mx0 = fmaxf(mx0, __shfl_xor_sync(0xffffffffu, mx0, 2));
        mx1 = fmaxf(mx1, __shfl_xor_sync(0xffffffffu, mx1, 1));
        mx1 = fmaxf(mx1, __shfl_xor_sync(0xffffffffu, mx1, 2));
        const float mn0 = fmaxf(mi0, mx0), mn1 = fmaxf(mi1, mx1);
        const float a0 = __expf(mi0 - mn0), a1 = __expf(mi1 - mn1);
        mi0 = mn0; mi1 = mn1;

        float sum0 = 0.0f, sum1 = 0.0f;
#pragma unroll
        for (int nt = 0; nt < 8; ++nt) {
            s_[nt][0] = __expf(s_[nt][0] - mn0);
            s_[nt][1] = __expf(s_[nt][1] - mn0);
            s_[nt][2] = __expf(s_[nt][2] - mn1);
            s_[nt][3] = __expf(s_[nt][3] - mn1);
            sum0 += s_[nt][0] + s_[nt][1];
            sum1 += s_[nt][2] + s_[nt][3];
        }
        sum0 += __shfl_xor_sync(0xffffffffu, sum0, 1);
        sum0 += __shfl_xor_sync(0xffffffffu, sum0, 2);
        sum1 += __shfl_xor_sync(0xffffffffu, sum1, 1);
        sum1 += __shfl_xor_sync(0xffffffffu, sum1, 2);
        li0 = li0 * a0 + sum0;
        li1 = li1 * a1 + sum1;

#pragma unroll
        for (int dt = 0; dt < 8; ++dt) {
            o[dt][0] *= a0; o[dt][1] *= a0;
            o[dt][2] *= a1; o[dt][3] *= a1;
        }

        // ---- O += P V (single-term fp16) ----
        const uint32_t vB = sb + (uint32_t)(buf * KVBUF_SZ) + laneOff;
#pragma unroll
        for (int st = 0; st < 4; ++st) {
            uint32_t pf[4];
            pf[0] = pack_f16(s_[2 * st][0],     s_[2 * st][1]);
            pf[1] = pack_f16(s_[2 * st][2],     s_[2 * st][3]);
            pf[2] = pack_f16(s_[2 * st + 1][0], s_[2 * st + 1][1]);
            pf[3] = pack_f16(s_[2 * st + 1][2], s_[2 * st + 1][3]);
#pragma unroll
            for (int j = 0; j < 4; ++j) {
                uint32_t vf[4];
                LDSM_X4_T(vf[0], vf[1], vf[2], vf[3],
                          vB + VF_OFF + st * (16 * APITCH) + j * 32);
                MMA_FP16(o[2 * j],     pf, vf[0], vf[1]);
                MMA_FP16(o[2 * j + 1], pf, vf[2], vf[3]);
            }
        }
        // single barrier per iteration (next store goes to the other buffer)
    }

    // ---- epilogue: normalize, write ctx (b, s, h*64+d) ----
    const int g  = lane >> 2;
    const int t2 = (lane & 3) * 2;
    const int row0 = q0 + wid * 16 + g;
    const int row1 = row0 + 8;
    const float inv0 = 1.0f / li0, inv1 = 1.0f / li1;
#pragma unroll
    for (int dt = 0; dt < 8; ++dt) {
        int col = h * DK + dt * 8 + t2;
        *(float2*)(ctx + (size_t)(b * S_LEN + row0) * DMODEL + col) =
            make_float2(o[dt][0] * inv0, o[dt][1] * inv0);
        *(float2*)(ctx + (size_t)(b * S_LEN + row1) * DMODEL + col) =
            make_float2(o[dt][2] * inv1, o[dt][3] * inv1);
    }
}

// ---------------------------------------------------------------------------
extern "C" void kernel_launch(void* const* d_in, const int* in_sizes, int n_in,
                              void* d_out, int out_size)
{
    const float* query = (const float*)d_in[0];
    const float* key   = (const float*)d_in[1];
    const float* value = (const float*)d_in[2];
    const int*   mask  = (const int*)d_in[3];
    const float* Wq = (const float*)d_in[4];
    const float* bq = (const float*)d_in[5];
    const float* Wk = (const float*)d_in[6];
    const float* bk = (const float*)d_in[7];
    const float* Wv = (const float*)d_in[8];
    const float* bv = (const float*)d_in[9];
    const float* Wo = (const float*)d_in[10];
    const float* bo = (const float*)d_in[11];
    float* out = (float*)d_out;

    float *Qd, *Kd, *Vd, *Cd;
    cudaGetSymbolAddress((void**)&Qd, g_Q);
    cudaGetSymbolAddress((void**)&Kd, g_K);
    cudaGetSymbolAddress((void**)&Vd, g_V);
    cudaGetSymbolAddress((void**)&Cd, g_ctx);

    cudaFuncSetAttribute(gemm_qkv, cudaFuncAttributeMaxDynamicSharedMemorySize, GEMM_SMEM);
    cudaFuncSetAttribute(gemm_out, cudaFuncAttributeMaxDynamicSharedMemorySize, GEMM_SMEM);
    cudaFuncSetAttribute(attn_mma, cudaFuncAttributeMaxDynamicSharedMemorySize, ATTN_SMEM);

    dim3 gq(DMODEL / 128, MTOT / 128, 3);       // (8, 32, 3) = 768 CTAs
    gemm_qkv<<<gq, 256, GEMM_SMEM>>>(query, key, value, Wq, Wk, Wv,
                                     bq, bk, bv, Qd, Kd, Vd);

    dim3 ag(S_LEN / 128, NHEADS, BATCH);        // (16, 16, 2) = 512 CTAs
    attn_mma<<<ag, 256, ATTN_SMEM>>>(Qd, Kd, Vd, mask, Cd);

    dim3 gg(DMODEL / 128, MTOT / 128);          // (8, 32) = 256 CTAs
    gemm_out<<<gg, 256, GEMM_SMEM>>>(Cd, Wo, bo, out);
}

// round 9
// speedup vs baseline: 1.6356x; 1.2889x over previous
#include <cuda_runtime.h>
#include <cuda_bf16.h>
#include <cstdint>

#define S_LEN   2048
#define BATCH   2
#define DMODEL  1024
#define NHEADS  16
#define DK      64
#define MTOT    (BATCH * S_LEN)   // 4096

// ---------------- scratch (static device globals; no dynamic allocation) ----
__device__ float g_Q[BATCH * NHEADS * S_LEN * DK];    // (b,h,s,d)
__device__ float g_K[BATCH * NHEADS * S_LEN * DK];
__device__ float g_V[BATCH * NHEADS * S_LEN * DK];
__device__ float g_ctx[MTOT * DMODEL];                // (b,s,h*d)

// ======================= warp-MMA helpers (portable PTX) ====================
__device__ __forceinline__ uint32_t smem_u32(const void* p) {
    uint32_t a;
    asm("{ .reg .u64 t; cvta.to.shared.u64 t, %1; cvt.u32.u64 %0, t; }"
        : "=r"(a) : "l"(p));
    return a;
}

#define LDSM_X4(r0, r1, r2, r3, addr) \
    asm volatile("ldmatrix.sync.aligned.m8n8.x4.shared.b16 {%0,%1,%2,%3}, [%4];" \
                 : "=r"(r0), "=r"(r1), "=r"(r2), "=r"(r3) : "r"(addr))

#define LDSM_X4_T(r0, r1, r2, r3, addr) \
    asm volatile("ldmatrix.sync.aligned.m8n8.x4.trans.shared.b16 {%0,%1,%2,%3}, [%4];" \
                 : "=r"(r0), "=r"(r1), "=r"(r2), "=r"(r3) : "r"(addr))

#define MMA_BF16(d, a, b0, b1) \
    asm volatile("mma.sync.aligned.m16n8k16.row.col.f32.bf16.bf16.f32 " \
                 "{%0,%1,%2,%3}, {%4,%5,%6,%7}, {%8,%9}, {%0,%1,%2,%3};" \
                 : "+f"((d)[0]), "+f"((d)[1]), "+f"((d)[2]), "+f"((d)[3]) \
                 : "r"((a)[0]), "r"((a)[1]), "r"((a)[2]), "r"((a)[3]), \
                   "r"(b0), "r"(b1))

#define MMA_FP16(d, a, b0, b1) \
    asm volatile("mma.sync.aligned.m16n8k16.row.col.f32.f16.f16.f32 " \
                 "{%0,%1,%2,%3}, {%4,%5,%6,%7}, {%8,%9}, {%0,%1,%2,%3};" \
                 : "+f"((d)[0]), "+f"((d)[1]), "+f"((d)[2]), "+f"((d)[3]) \
                 : "r"((a)[0]), "r"((a)[1]), "r"((a)[2]), "r"((a)[3]), \
                   "r"(b0), "r"(b1))

__device__ __forceinline__ void split_f4(float4 v, uint2& hi, uint2& lo) {
    uint32_t hA, hB, lA, lB;
    asm("cvt.rn.bf16x2.f32 %0, %1, %2;" : "=r"(hA) : "f"(v.y), "f"(v.x));
    asm("cvt.rn.bf16x2.f32 %0, %1, %2;" : "=r"(hB) : "f"(v.w), "f"(v.z));
    float f0 = __uint_as_float(hA << 16), f1 = __uint_as_float(hA & 0xFFFF0000u);
    float f2 = __uint_as_float(hB << 16), f3 = __uint_as_float(hB & 0xFFFF0000u);
    asm("cvt.rn.bf16x2.f32 %0, %1, %2;" : "=r"(lA) : "f"(v.y - f1), "f"(v.x - f0));
    asm("cvt.rn.bf16x2.f32 %0, %1, %2;" : "=r"(lB) : "f"(v.w - f3), "f"(v.z - f2));
    hi = make_uint2(hA, hB);
    lo = make_uint2(lA, lB);
}

__device__ __forceinline__ uint32_t pack_f16(float a, float b) {   // low = a
    uint32_t r;
    asm("cvt.rn.f16x2.f32 %0, %1, %2;" : "=r"(r) : "f"(b), "f"(a));
    return r;
}
__device__ __forceinline__ uint2 pack_f4(float4 v) {
    return make_uint2(pack_f16(v.x, v.y), pack_f16(v.z, v.w));
}

// ======================= 3-term split-bf16 GEMM (QKV projections) ==========
#define PITCH_B   48
#define SL_SZ     6144
#define AH_OFF    0
#define AL_OFF    12288
#define WH_OFF    24576
#define WL_OFF    36864
#define BUF_SZ    49152
#define GEMM_SMEM (2 * BUF_SZ)

__device__ __forceinline__ void gemm_body_split(
    const float* __restrict__ A, const float* __restrict__ W,
    const float* __restrict__ bias, float* __restrict__ C, char* smem)
{
    const uint32_t sb = smem_u32(smem);
    const int tid  = threadIdx.x;
    const int lane = tid & 31;
    const int wid  = tid >> 5;
    const int wm   = wid >> 2;
    const int wn   = wid & 3;
    const int m0   = blockIdx.y * 128;
    const int n0   = blockIdx.x * 128;

    const uint32_t laneOff = (uint32_t)((lane & 15) * PITCH_B + (lane >> 4) * 16);

    float acc[4][4][4];
#pragma unroll
    for (int i = 0; i < 4; ++i)
#pragma unroll
        for (int j = 0; j < 4; ++j)
#pragma unroll
            for (int r = 0; r < 4; ++r) acc[i][j][r] = 0.0f;

    float4 pa[4], pw[4];
#pragma unroll
    for (int i = 0; i < 4; ++i) {
        int slot = i * 256 + tid;
        int row  = slot >> 3;
        int q    = (slot & 7) << 2;
        pa[i] = *(const float4*)(A + (size_t)(m0 + row) * DMODEL + q);
        pw[i] = *(const float4*)(W + (size_t)(n0 + row) * DMODEL + q);
    }

#pragma unroll 1
    for (int ch = 0; ch < 32; ++ch) {
        char* sp = smem + (ch & 1) * BUF_SZ;

#pragma unroll
        for (int i = 0; i < 4; ++i) {
            int slot = i * 256 + tid;
            int row  = slot >> 3;
            int q    = (slot & 7) << 2;
            int soff = (q >> 4) * SL_SZ + row * PITCH_B + (q & 15) * 2;
            uint2 hi, lo;
            split_f4(pa[i], hi, lo);
            *(uint2*)(sp + AH_OFF + soff) = hi;
            *(uint2*)(sp + AL_OFF + soff) = lo;
            split_f4(pw[i], hi, lo);
            *(uint2*)(sp + WH_OFF + soff) = hi;
            *(uint2*)(sp + WL_OFF + soff) = lo;
        }
        __syncthreads();

        if (ch + 1 < 32) {
            const int kt = (ch + 1) * 32;
#pragma unroll
            for (int i = 0; i < 4; ++i) {
                int slot = i * 256 + tid;
                int row  = slot >> 3;
                int q    = (slot & 7) << 2;
                pa[i] = *(const float4*)(A + (size_t)(m0 + row) * DMODEL + kt + q);
                pw[i] = *(const float4*)(W + (size_t)(n0 + row) * DMODEL + kt + q);
            }
        }

        const uint32_t bufb = sb + (uint32_t)((ch & 1) * BUF_SZ);
        const uint32_t aBase = bufb + (uint32_t)(wm * 64) * PITCH_B + laneOff;
        const uint32_t wBase = bufb + (uint32_t)(wn * 32) * PITCH_B + laneOff;

#pragma unroll
        for (int ks = 0; ks < 2; ++ks) {
            const uint32_t so = (uint32_t)ks * SL_SZ;
            uint32_t ah[4][4], wh[2][4], tmp[2][4];
#pragma unroll
            for (int mt = 0; mt < 4; ++mt)
                LDSM_X4(ah[mt][0], ah[mt][1], ah[mt][2], ah[mt][3],
                        aBase + AH_OFF + so + mt * 16 * PITCH_B);
#pragma unroll
            for (int n2 = 0; n2 < 2; ++n2)
                LDSM_X4(wh[n2][0], wh[n2][1], wh[n2][2], wh[n2][3],
                        wBase + WH_OFF + so + n2 * 16 * PITCH_B);
#pragma unroll
            for (int mt = 0; mt < 4; ++mt)
#pragma unroll
                for (int nt = 0; nt < 4; ++nt)
                    MMA_BF16(acc[mt][nt], ah[mt],
                             wh[nt >> 1][nt & 1], wh[nt >> 1][(nt & 1) + 2]);
#pragma unroll
            for (int n2 = 0; n2 < 2; ++n2)
                LDSM_X4(tmp[n2][0], tmp[n2][1], tmp[n2][2], tmp[n2][3],
                        wBase + WL_OFF + so + n2 * 16 * PITCH_B);
#pragma unroll
            for (int mt = 0; mt < 4; ++mt)
#pragma unroll
                for (int nt = 0; nt < 4; ++nt)
                    MMA_BF16(acc[mt][nt], ah[mt],
                             tmp[nt >> 1][nt & 1], tmp[nt >> 1][(nt & 1) + 2]);
#pragma unroll
            for (int mt = 0; mt < 4; ++mt) {
                uint32_t al[4];
                LDSM_X4(al[0], al[1], al[2], al[3],
                        aBase + AL_OFF + so + mt * 16 * PITCH_B);
#pragma unroll
                for (int nt = 0; nt < 4; ++nt)
                    MMA_BF16(acc[mt][nt], al,
                             wh[nt >> 1][nt & 1], wh[nt >> 1][(nt & 1) + 2]);
            }
        }
    }

    // head-major (b,h,s,d) epilogue with bias
    const int group = lane >> 2;
    const int tcol  = (lane & 3) * 2;
#pragma unroll
    for (int mt = 0; mt < 4; ++mt) {
#pragma unroll
        for (int nt = 0; nt < 4; ++nt) {
            int row = m0 + wm * 64 + mt * 16 + group;
            int col = n0 + wn * 32 + nt * 8 + tcol;
            float bx = bias[col], by = bias[col + 1];
            float2 v0 = make_float2(acc[mt][nt][0] + bx, acc[mt][nt][1] + by);
            float2 v1 = make_float2(acc[mt][nt][2] + bx, acc[mt][nt][3] + by);
            int h = col >> 6, d = col & 63;
            int b0_ = row >> 11, s0_ = row & 2047;
            int b1_ = (row + 8) >> 11, s1_ = (row + 8) & 2047;
            *(float2*)(C + (((size_t)(b0_ * NHEADS + h) * S_LEN + s0_) * DK) + d) = v0;
            *(float2*)(C + (((size_t)(b1_ * NHEADS + h) * S_LEN + s1_) * DK) + d) = v1;
        }
    }
}

__global__ void __launch_bounds__(256, 2) gemm_qkv(
    const float* __restrict__ q, const float* __restrict__ k,
    const float* __restrict__ v,
    const float* __restrict__ Wq, const float* __restrict__ Wk,
    const float* __restrict__ Wv,
    const float* __restrict__ bq, const float* __restrict__ bk,
    const float* __restrict__ bv,
    float* __restrict__ Qd, float* __restrict__ Kd, float* __restrict__ Vd)
{
    extern __shared__ __align__(128) char smem[];
    const float *A, *W, *bias;
    float* C;
    if (blockIdx.z == 0)      { A = q; W = Wq; bias = bq; C = Qd; }
    else if (blockIdx.z == 1) { A = k; W = Wk; bias = bk; C = Kd; }
    else                      { A = v; W = Wv; bias = bv; C = Vd; }
    gemm_body_split(A, W, bias, C, smem);
}

// ======================= single-term fp16 GEMM (output projection) =========
#define F16A_OFF  0
#define F16W_OFF  12288
#define F16BUF_SZ 24576
#define OUT_SMEM  (2 * F16BUF_SZ)   // 49152

__global__ void __launch_bounds__(256, 2) gemm_out_f16(
    const float* __restrict__ A, const float* __restrict__ W,
    const float* __restrict__ bias, float* __restrict__ C)
{
    extern __shared__ __align__(128) char smem[];
    const uint32_t sb = smem_u32(smem);
    const int tid  = threadIdx.x;
    const int lane = tid & 31;
    const int wid  = tid >> 5;
    const int wm   = wid >> 2;
    const int wn   = wid & 3;
    const int m0   = blockIdx.y * 128;
    const int n0   = blockIdx.x * 128;

    const uint32_t laneOff = (uint32_t)((lane & 15) * PITCH_B + (lane >> 4) * 16);

    float acc[4][4][4];
#pragma unroll
    for (int i = 0; i < 4; ++i)
#pragma unroll
        for (int j = 0; j < 4; ++j)
#pragma unroll
            for (int r = 0; r < 4; ++r) acc[i][j][r] = 0.0f;

    float4 pa[4], pw[4];
#pragma unroll
    for (int i = 0; i < 4; ++i) {
        int slot = i * 256 + tid;
        int row  = slot >> 3;
        int q    = (slot & 7) << 2;
        pa[i] = *(const float4*)(A + (size_t)(m0 + row) * DMODEL + q);
        pw[i] = *(const float4*)(W + (size_t)(n0 + row) * DMODEL + q);
    }

#pragma unroll 1
    for (int ch = 0; ch < 32; ++ch) {
        char* sp = smem + (ch & 1) * F16BUF_SZ;

#pragma unroll
        for (int i = 0; i < 4; ++i) {
            int slot = i * 256 + tid;
            int row  = slot >> 3;
            int q    = (slot & 7) << 2;
            int soff = (q >> 4) * SL_SZ + row * PITCH_B + (q & 15) * 2;
            *(uint2*)(sp + F16A_OFF + soff) = pack_f4(pa[i]);
            *(uint2*)(sp + F16W_OFF + soff) = pack_f4(pw[i]);
        }
        __syncthreads();

        if (ch + 1 < 32) {
            const int kt = (ch + 1) * 32;
#pragma unroll
            for (int i = 0; i < 4; ++i) {
                int slot = i * 256 + tid;
                int row  = slot >> 3;
                int q    = (slot & 7) << 2;
                pa[i] = *(const float4*)(A + (size_t)(m0 + row) * DMODEL + kt + q);
                pw[i] = *(const float4*)(W + (size_t)(n0 + row) * DMODEL + kt + q);
            }
        }

        const uint32_t bufb = sb + (uint32_t)((ch & 1) * F16BUF_SZ);
        const uint32_t aBase = bufb + (uint32_t)(wm * 64) * PITCH_B + laneOff;
        const uint32_t wBase = bufb + (uint32_t)(wn * 32) * PITCH_B + laneOff;

#pragma unroll
        for (int ks = 0; ks < 2; ++ks) {
            const uint32_t so = (uint32_t)ks * SL_SZ;
            uint32_t ah[4][4], wh[2][4];
#pragma unroll
            for (int mt = 0; mt < 4; ++mt)
                LDSM_X4(ah[mt][0], ah[mt][1], ah[mt][2], ah[mt][3],
                        aBase + F16A_OFF + so + mt * 16 * PITCH_B);
#pragma unroll
            for (int n2 = 0; n2 < 2; ++n2)
                LDSM_X4(wh[n2][0], wh[n2][1], wh[n2][2], wh[n2][3],
                        wBase + F16W_OFF + so + n2 * 16 * PITCH_B);
#pragma unroll
            for (int mt = 0; mt < 4; ++mt)
#pragma unroll
                for (int nt = 0; nt < 4; ++nt)
                    MMA_FP16(acc[mt][nt], ah[mt],
                             wh[nt >> 1][nt & 1], wh[nt >> 1][(nt & 1) + 2]);
        }
    }

    const int group = lane >> 2;
    const int tcol  = (lane & 3) * 2;
#pragma unroll
    for (int mt = 0; mt < 4; ++mt) {
#pragma unroll
        for (int nt = 0; nt < 4; ++nt) {
            int row = m0 + wm * 64 + mt * 16 + group;
            int col = n0 + wn * 32 + nt * 8 + tcol;
            float bx = bias[col], by = bias[col + 1];
            *(float2*)(C + (size_t)row * DMODEL + col) =
                make_float2(acc[mt][nt][0] + bx, acc[mt][nt][1] + by);
            *(float2*)(C + (size_t)(row + 8) * DMODEL + col) =
                make_float2(acc[mt][nt][2] + bx, acc[mt][nt][3] + by);
        }
    }
}

// ======================= HMMA flash attention (all fp16 operands) ==========
// QK: single fp16 (Q pre-scaled 1/8).  PV: single fp16.  fp32 accum + softmax.
#define APITCH    144
#define KF_OFF    0
#define VF_OFF    9216
#define KVBUF_SZ  18432
#define QF_OFF    36864
#define MASK_OFF  55296
#define ATTN_SMEM (MASK_OFF + 2 * 64 * 4)   // 55808

__global__ void __launch_bounds__(256, 2) attn_mma(
    const float* __restrict__ Q, const float* __restrict__ K,
    const float* __restrict__ V, const int* __restrict__ mask,
    float* __restrict__ ctx)
{
    extern __shared__ __align__(128) char smem[];
    const uint32_t sb = smem_u32(smem);
    const int tid  = threadIdx.x;
    const int lane = tid & 31;
    const int wid  = tid >> 5;
    const int q0   = blockIdx.x * 128;
    const int h    = blockIdx.y;
    const int b    = blockIdx.z;
    const size_t base = (size_t)(b * NHEADS + h) * S_LEN * DK;

    const uint32_t laneOff = (uint32_t)((lane & 15) * APITCH + (lane >> 4) * 16);

    // ---- stage Q (scaled by 1/8) as fp16 ----
#pragma unroll
    for (int i = 0; i < 8; ++i) {
        int slot = i * 256 + tid;
        int row  = slot >> 4;
        int dq   = (slot & 15) << 2;
        float4 v = *(const float4*)(Q + base + (size_t)(q0 + row) * DK + dq);
        v.x *= 0.125f; v.y *= 0.125f; v.z *= 0.125f; v.w *= 0.125f;
        *(uint2*)(smem + QF_OFF + row * APITCH + dq * 2) = pack_f4(v);
    }

    // prefetch K/V tile 0
    float4 pk[4], pv[4];
#pragma unroll
    for (int i = 0; i < 4; ++i) {
        int slot = i * 256 + tid;
        int row  = slot >> 4;
        int dq   = (slot & 15) << 2;
        size_t goff = base + (size_t)row * DK + dq;
        pk[i] = *(const float4*)(K + goff);
        pv[i] = *(const float4*)(V + goff);
    }
    __syncthreads();

    uint32_t qf[4][4];
    {
        const uint32_t qB = sb + QF_OFF + (uint32_t)(wid * 16) * APITCH + laneOff;
#pragma unroll
        for (int s = 0; s < 4; ++s)
            LDSM_X4(qf[s][0], qf[s][1], qf[s][2], qf[s][3], qB + s * 32);
    }

    float o[8][4];
#pragma unroll
    for (int dt = 0; dt < 8; ++dt)
#pragma unroll
        for (int r = 0; r < 4; ++r) o[dt][r] = 0.0f;
    float mi0 = -1.0e30f, mi1 = -1.0e30f, li0 = 0.0f, li1 = 0.0f;

#pragma unroll 1
    for (int t = 0; t < 32; ++t) {
        const int buf = t & 1;
        char* sp = smem + buf * KVBUF_SZ;

        // ---- store prefetched K/V (fp16) ----
#pragma unroll
        for (int i = 0; i < 4; ++i) {
            int slot = i * 256 + tid;
            int row  = slot >> 4;
            int dq   = (slot & 15) << 2;
            int soff = row * APITCH + dq * 2;
            *(uint2*)(sp + KF_OFF + soff) = pack_f4(pk[i]);
            *(uint2*)(sp + VF_OFF + soff) = pack_f4(pv[i]);
        }
        if (tid < 64)
            ((int*)(smem + MASK_OFF))[buf * 64 + tid] = mask[b * S_LEN + t * 64 + tid];
        __syncthreads();

        if (t + 1 < 32) {
            const int k1 = (t + 1) * 64;
#pragma unroll
            for (int i = 0; i < 4; ++i) {
                int slot = i * 256 + tid;
                int row  = slot >> 4;
                int dq   = (slot & 15) << 2;
                size_t goff = base + (size_t)(k1 + row) * DK + dq;
                pk[i] = *(const float4*)(K + goff);
                pv[i] = *(const float4*)(V + goff);
            }
        }

        // ---- S = Q K^T (single fp16) ----
        float s_[8][4];
#pragma unroll
        for (int nt = 0; nt < 8; ++nt)
#pragma unroll
            for (int r = 0; r < 4; ++r) s_[nt][r] = 0.0f;

        const uint32_t kB = sb + (uint32_t)(buf * KVBUF_SZ) + laneOff;
#pragma unroll
        for (int st = 0; st < 4; ++st) {
#pragma unroll
            for (int g2 = 0; g2 < 4; ++g2) {
                uint32_t kf[4];
                LDSM_X4(kf[0], kf[1], kf[2], kf[3],
                        kB + KF_OFF + g2 * (16 * APITCH) + st * 32);
                MMA_FP16(s_[2 * g2],     qf[st], kf[0], kf[2]);
                MMA_FP16(s_[2 * g2 + 1], qf[st], kf[1], kf[3]);
            }
        }

        // ---- mask ----
        const int* mbuf = (const int*)(smem + MASK_OFF) + buf * 64;
#pragma unroll
        for (int nt = 0; nt < 8; ++nt) {
            int2 mv = *(const int2*)&mbuf[nt * 8 + (lane & 3) * 2];
            if (mv.x == 0) { s_[nt][0] = -1.0e9f; s_[nt][2] = -1.0e9f; }
            if (mv.y == 0) { s_[nt][1] = -1.0e9f; s_[nt][3] = -1.0e9f; }
        }

        // ---- online softmax ----
        float mx0 = -1.0e30f, mx1 = -1.0e30f;
#pragma unroll
        for (int nt = 0; nt < 8; ++nt) {
            mx0 = fmaxf(mx0, fmaxf(s_[nt][0], s_[nt][1]));
            mx1 = fmaxf(mx1, fmaxf(s_[nt][2], s_[nt][3]));
        }
        mx0 = fmaxf(mx0, __shfl_xor_sync(0xffffffffu, mx0, 1));
        mx0 = fmaxf(mx0, __shfl_xor_sync(0xffffffffu, mx0, 2));
        mx1 = fmaxf(mx1, __shfl_xor_sync(0xffffffffu, mx1, 1));
        mx1 = fmaxf(mx1, __shfl_xor_sync(0xffffffffu, mx1, 2));
        const float mn0 = fmaxf(mi0, mx0), mn1 = fmaxf(mi1, mx1);
        const float a0 = __expf(mi0 - mn0), a1 = __expf(mi1 - mn1);
        mi0 = mn0; mi1 = mn1;

        float sum0 = 0.0f, sum1 = 0.0f;
#pragma unroll
        for (int nt = 0; nt < 8; ++nt) {
            s_[nt][0] = __expf(s_[nt][0] - mn0);
            s_[nt][1] = __expf(s_[nt][1] - mn0);
            s_[nt][2] = __expf(s_[nt][2] - mn1);
            s_[nt][3] = __expf(s_[nt][3] - mn1);
            sum0 += s_[nt][0] + s_[nt][1];
            sum1 += s_[nt][2] + s_[nt][3];
        }
        sum0 += __shfl_xor_sync(0xffffffffu, sum0, 1);
        sum0 += __shfl_xor_sync(0xffffffffu, sum0, 2);
        sum1 += __shfl_xor_sync(0xffffffffu, sum1, 1);
        sum1 += __shfl_xor_sync(0xffffffffu, sum1, 2);
        li0 = li0 * a0 + sum0;
        li1 = li1 * a1 + sum1;

#pragma unroll
        for (int dt = 0; dt < 8; ++dt) {
            o[dt][0] *= a0; o[dt][1] *= a0;
            o[dt][2] *= a1; o[dt][3] *= a1;
        }

        // ---- O += P V (single fp16) ----
        const uint32_t vB = sb + (uint32_t)(buf * KVBUF_SZ) + laneOff;
#pragma unroll
        for (int st = 0; st < 4; ++st) {
            uint32_t pf[4];
            pf[0] = pack_f16(s_[2 * st][0],     s_[2 * st][1]);
            pf[1] = pack_f16(s_[2 * st][2],     s_[2 * st][3]);
            pf[2] = pack_f16(s_[2 * st + 1][0], s_[2 * st + 1][1]);
            pf[3] = pack_f16(s_[2 * st + 1][2], s_[2 * st + 1][3]);
#pragma unroll
            for (int j = 0; j < 4; ++j) {
                uint32_t vf[4];
                LDSM_X4_T(vf[0], vf[1], vf[2], vf[3],
                          vB + VF_OFF + st * (16 * APITCH) + j * 32);
                MMA_FP16(o[2 * j],     pf, vf[0], vf[1]);
                MMA_FP16(o[2 * j + 1], pf, vf[2], vf[3]);
            }
        }
        // single barrier per iteration (next store goes to the other buffer)
    }

    // ---- epilogue: normalize, write ctx (b, s, h*64+d) ----
    const int g  = lane >> 2;
    const int t2 = (lane & 3) * 2;
    const int row0 = q0 + wid * 16 + g;
    const int row1 = row0 + 8;
    const float inv0 = 1.0f / li0, inv1 = 1.0f / li1;
#pragma unroll
    for (int dt = 0; dt < 8; ++dt) {
        int col = h * DK + dt * 8 + t2;
        *(float2*)(ctx + (size_t)(b * S_LEN + row0) * DMODEL + col) =
            make_float2(o[dt][0] * inv0, o[dt][1] * inv0);
        *(float2*)(ctx + (size_t)(b * S_LEN + row1) * DMODEL + col) =
            make_float2(o[dt][2] * inv1, o[dt][3] * inv1);
    }
}

// ---------------------------------------------------------------------------
extern "C" void kernel_launch(void* const* d_in, const int* in_sizes, int n_in,
                              void* d_out, int out_size)
{
    const float* query = (const float*)d_in[0];
    const float* key   = (const float*)d_in[1];
    const float* value = (const float*)d_in[2];
    const int*   mask  = (const int*)d_in[3];
    const float* Wq = (const float*)d_in[4];
    const float* bq = (const float*)d_in[5];
    const float* Wk = (const float*)d_in[6];
    const float* bk = (const float*)d_in[7];
    const float* Wv = (const float*)d_in[8];
    const float* bv = (const float*)d_in[9];
    const float* Wo = (const float*)d_in[10];
    const float* bo = (const float*)d_in[11];
    float* out = (float*)d_out;

    float *Qd, *Kd, *Vd, *Cd;
    cudaGetSymbolAddress((void**)&Qd, g_Q);
    cudaGetSymbolAddress((void**)&Kd, g_K);
    cudaGetSymbolAddress((void**)&Vd, g_V);
    cudaGetSymbolAddress((void**)&Cd, g_ctx);

    cudaFuncSetAttribute(gemm_qkv, cudaFuncAttributeMaxDynamicSharedMemorySize, GEMM_SMEM);
    cudaFuncSetAttribute(gemm_out_f16, cudaFuncAttributeMaxDynamicSharedMemorySize, OUT_SMEM);
    cudaFuncSetAttribute(attn_mma, cudaFuncAttributeMaxDynamicSharedMemorySize, ATTN_SMEM);

    dim3 gq(DMODEL / 128, MTOT / 128, 3);       // (8, 32, 3) = 768 CTAs
    gemm_qkv<<<gq, 256, GEMM_SMEM>>>(query, key, value, Wq, Wk, Wv,
                                     bq, bk, bv, Qd, Kd, Vd);

    dim3 ag(S_LEN / 128, NHEADS, BATCH);        // (16, 16, 2) = 512 CTAs
    attn_mma<<<ag, 256, ATTN_SMEM>>>(Qd, Kd, Vd, mask, Cd);

    dim3 gg(DMODEL / 128, MTOT / 128);          // (8, 32) = 256 CTAs
    gemm_out_f16<<<gg, 256, OUT_SMEM>>>(Cd, Wo, bo, out);
}

// round 10
// speedup vs baseline: 1.9092x; 1.1672x over previous
#include <cuda_runtime.h>
#include <cuda_bf16.h>
#include <cuda_fp16.h>
#include <cstdint>

#define S_LEN   2048
#define BATCH   2
#define DMODEL  1024
#define NHEADS  16
#define DK      64
#define MTOT    (BATCH * S_LEN)   // 4096

// ---------------- scratch (static device globals; no dynamic allocation) ----
__device__ float g_Q[BATCH * NHEADS * S_LEN * DK];    // (b,h,s,d)
__device__ float g_K[BATCH * NHEADS * S_LEN * DK];
__device__ float g_V[BATCH * NHEADS * S_LEN * DK];
__device__ float g_ctx[MTOT * DMODEL];                // (b,s,h*d)

// ======================= warp-MMA helpers (portable PTX) ====================
__device__ __forceinline__ uint32_t smem_u32(const void* p) {
    uint32_t a;
    asm("{ .reg .u64 t; cvta.to.shared.u64 t, %1; cvt.u32.u64 %0, t; }"
        : "=r"(a) : "l"(p));
    return a;
}

#define LDSM_X4(r0, r1, r2, r3, addr) \
    asm volatile("ldmatrix.sync.aligned.m8n8.x4.shared.b16 {%0,%1,%2,%3}, [%4];" \
                 : "=r"(r0), "=r"(r1), "=r"(r2), "=r"(r3) : "r"(addr))

#define LDSM_X4_T(r0, r1, r2, r3, addr) \
    asm volatile("ldmatrix.sync.aligned.m8n8.x4.trans.shared.b16 {%0,%1,%2,%3}, [%4];" \
                 : "=r"(r0), "=r"(r1), "=r"(r2), "=r"(r3) : "r"(addr))

#define MMA_FP16(d, a, b0, b1) \
    asm volatile("mma.sync.aligned.m16n8k16.row.col.f32.f16.f16.f32 " \
                 "{%0,%1,%2,%3}, {%4,%5,%6,%7}, {%8,%9}, {%0,%1,%2,%3};" \
                 : "+f"((d)[0]), "+f"((d)[1]), "+f"((d)[2]), "+f"((d)[3]) \
                 : "r"((a)[0]), "r"((a)[1]), "r"((a)[2]), "r"((a)[3]), \
                   "r"(b0), "r"(b1))

__device__ __forceinline__ uint32_t pack_f16(float a, float b) {   // low = a
    uint32_t r;
    asm("cvt.rn.f16x2.f32 %0, %1, %2;" : "=r"(r) : "f"(b), "f"(a));
    return r;
}
__device__ __forceinline__ uint2 pack_f4(float4 v) {
    return make_uint2(pack_f16(v.x, v.y), pack_f16(v.z, v.w));
}
// exact fp16 hi/lo split of a float4 (hi + lo reproduces fp32 to ~2^-22)
__device__ __forceinline__ void split_f4_f16(float4 v, uint2& hi, uint2& lo) {
    uint32_t h0 = pack_f16(v.x, v.y);
    uint32_t h1 = pack_f16(v.z, v.w);
    half2 a = *(half2*)&h0;
    half2 b = *(half2*)&h1;
    uint32_t l0 = pack_f16(v.x - __low2float(a), v.y - __high2float(a));
    uint32_t l1 = pack_f16(v.z - __low2float(b), v.w - __high2float(b));
    hi = make_uint2(h0, h1);
    lo = make_uint2(l0, l1);
}

// ======================= 2-term fp16 GEMM (QKV projections) ================
// A split exact (f16 hi/lo), W single f16.  acc += Ah*Wf + Al*Wf.
#define PITCH_B   48
#define SL_SZ     6144
#define QAH_OFF   0
#define QAL_OFF   12288
#define QWF_OFF   24576
#define QBUF_SZ   36864
#define QKV_SMEM  (2 * QBUF_SZ)   // 73728

__global__ void __launch_bounds__(256, 2) gemm_qkv(
    const float* __restrict__ q, const float* __restrict__ k,
    const float* __restrict__ v,
    const float* __restrict__ Wq, const float* __restrict__ Wk,
    const float* __restrict__ Wv,
    const float* __restrict__ bq, const float* __restrict__ bk,
    const float* __restrict__ bv,
    float* __restrict__ Qd, float* __restrict__ Kd, float* __restrict__ Vd)
{
    extern __shared__ __align__(128) char smem[];
    const float *A, *W, *bias;
    float* C;
    if (blockIdx.z == 0)      { A = q; W = Wq; bias = bq; C = Qd; }
    else if (blockIdx.z == 1) { A = k; W = Wk; bias = bk; C = Kd; }
    else                      { A = v; W = Wv; bias = bv; C = Vd; }

    const uint32_t sb = smem_u32(smem);
    const int tid  = threadIdx.x;
    const int lane = tid & 31;
    const int wid  = tid >> 5;
    const int wm   = wid >> 2;
    const int wn   = wid & 3;
    const int m0   = blockIdx.y * 128;
    const int n0   = blockIdx.x * 128;

    const uint32_t laneOff = (uint32_t)((lane & 15) * PITCH_B + (lane >> 4) * 16);

    float acc[4][4][4];
#pragma unroll
    for (int i = 0; i < 4; ++i)
#pragma unroll
        for (int j = 0; j < 4; ++j)
#pragma unroll
            for (int r = 0; r < 4; ++r) acc[i][j][r] = 0.0f;

    float4 pa[4], pw[4];
#pragma unroll
    for (int i = 0; i < 4; ++i) {
        int slot = i * 256 + tid;
        int row  = slot >> 3;
        int qo   = (slot & 7) << 2;
        pa[i] = *(const float4*)(A + (size_t)(m0 + row) * DMODEL + qo);
        pw[i] = *(const float4*)(W + (size_t)(n0 + row) * DMODEL + qo);
    }

#pragma unroll 1
    for (int ch = 0; ch < 32; ++ch) {
        char* sp = smem + (ch & 1) * QBUF_SZ;

#pragma unroll
        for (int i = 0; i < 4; ++i) {
            int slot = i * 256 + tid;
            int row  = slot >> 3;
            int qo   = (slot & 7) << 2;
            int soff = (qo >> 4) * SL_SZ + row * PITCH_B + (qo & 15) * 2;
            uint2 hi, lo;
            split_f4_f16(pa[i], hi, lo);
            *(uint2*)(sp + QAH_OFF + soff) = hi;
            *(uint2*)(sp + QAL_OFF + soff) = lo;
            *(uint2*)(sp + QWF_OFF + soff) = pack_f4(pw[i]);
        }
        __syncthreads();

        if (ch + 1 < 32) {
            const int kt = (ch + 1) * 32;
#pragma unroll
            for (int i = 0; i < 4; ++i) {
                int slot = i * 256 + tid;
                int row  = slot >> 3;
                int qo   = (slot & 7) << 2;
                pa[i] = *(const float4*)(A + (size_t)(m0 + row) * DMODEL + kt + qo);
                pw[i] = *(const float4*)(W + (size_t)(n0 + row) * DMODEL + kt + qo);
            }
        }

        const uint32_t bufb = sb + (uint32_t)((ch & 1) * QBUF_SZ);
        const uint32_t aBase = bufb + (uint32_t)(wm * 64) * PITCH_B + laneOff;
        const uint32_t wBase = bufb + (uint32_t)(wn * 32) * PITCH_B + laneOff;

#pragma unroll
        for (int ks = 0; ks < 2; ++ks) {
            const uint32_t so = (uint32_t)ks * SL_SZ;
            uint32_t ah[4][4], wf[2][4];
#pragma unroll
            for (int mt = 0; mt < 4; ++mt)
                LDSM_X4(ah[mt][0], ah[mt][1], ah[mt][2], ah[mt][3],
                        aBase + QAH_OFF + so + mt * 16 * PITCH_B);
#pragma unroll
            for (int n2 = 0; n2 < 2; ++n2)
                LDSM_X4(wf[n2][0], wf[n2][1], wf[n2][2], wf[n2][3],
                        wBase + QWF_OFF + so + n2 * 16 * PITCH_B);
#pragma unroll
            for (int mt = 0; mt < 4; ++mt)
#pragma unroll
                for (int nt = 0; nt < 4; ++nt)
                    MMA_FP16(acc[mt][nt], ah[mt],
                             wf[nt >> 1][nt & 1], wf[nt >> 1][(nt & 1) + 2]);
#pragma unroll
            for (int mt = 0; mt < 4; ++mt) {
                uint32_t al[4];
                LDSM_X4(al[0], al[1], al[2], al[3],
                        aBase + QAL_OFF + so + mt * 16 * PITCH_B);
#pragma unroll
                for (int nt = 0; nt < 4; ++nt)
                    MMA_FP16(acc[mt][nt], al,
                             wf[nt >> 1][nt & 1], wf[nt >> 1][(nt & 1) + 2]);
            }
        }
    }

    // head-major (b,h,s,d) epilogue with bias
    const int group = lane >> 2;
    const int tcol  = (lane & 3) * 2;
#pragma unroll
    for (int mt = 0; mt < 4; ++mt) {
#pragma unroll
        for (int nt = 0; nt < 4; ++nt) {
            int row = m0 + wm * 64 + mt * 16 + group;
            int col = n0 + wn * 32 + nt * 8 + tcol;
            float bx = bias[col], by = bias[col + 1];
            float2 v0 = make_float2(acc[mt][nt][0] + bx, acc[mt][nt][1] + by);
            float2 v1 = make_float2(acc[mt][nt][2] + bx, acc[mt][nt][3] + by);
            int h = col >> 6, d = col & 63;
            int b0_ = row >> 11, s0_ = row & 2047;
            int b1_ = (row + 8) >> 11, s1_ = (row + 8) & 2047;
            *(float2*)(C + (((size_t)(b0_ * NHEADS + h) * S_LEN + s0_) * DK) + d) = v0;
            *(float2*)(C + (((size_t)(b1_ * NHEADS + h) * S_LEN + s1_) * DK) + d) = v1;
        }
    }
}

// ======================= single-term fp16 GEMM (output projection) =========
#define F16A_OFF  0
#define F16W_OFF  12288
#define F16BUF_SZ 24576
#define OUT_SMEM  (2 * F16BUF_SZ)   // 49152

__global__ void __launch_bounds__(256, 2) gemm_out_f16(
    const float* __restrict__ A, const float* __restrict__ W,
    const float* __restrict__ bias, float* __restrict__ C)
{
    extern __shared__ __align__(128) char smem[];
    const uint32_t sb = smem_u32(smem);
    const int tid  = threadIdx.x;
    const int lane = tid & 31;
    const int wid  = tid >> 5;
    const int wm   = wid >> 2;
    const int wn   = wid & 3;
    const int m0   = blockIdx.y * 128;
    const int n0   = blockIdx.x * 128;

    const uint32_t laneOff = (uint32_t)((lane & 15) * PITCH_B + (lane >> 4) * 16);

    float acc[4][4][4];
#pragma unroll
    for (int i = 0; i < 4; ++i)
#pragma unroll
        for (int j = 0; j < 4; ++j)
#pragma unroll
            for (int r = 0; r < 4; ++r) acc[i][j][r] = 0.0f;

    float4 pa[4], pw[4];
#pragma unroll
    for (int i = 0; i < 4; ++i) {
        int slot = i * 256 + tid;
        int row  = slot >> 3;
        int q    = (slot & 7) << 2;
        pa[i] = *(const float4*)(A + (size_t)(m0 + row) * DMODEL + q);
        pw[i] = *(const float4*)(W + (size_t)(n0 + row) * DMODEL + q);
    }

#pragma unroll 1
    for (int ch = 0; ch < 32; ++ch) {
        char* sp = smem + (ch & 1) * F16BUF_SZ;

#pragma unroll
        for (int i = 0; i < 4; ++i) {
            int slot = i * 256 + tid;
            int row  = slot >> 3;
            int q    = (slot & 7) << 2;
            int soff = (q >> 4) * SL_SZ + row * PITCH_B + (q & 15) * 2;
            *(uint2*)(sp + F16A_OFF + soff) = pack_f4(pa[i]);
            *(uint2*)(sp + F16W_OFF + soff) = pack_f4(pw[i]);
        }
        __syncthreads();

        if (ch + 1 < 32) {
            const int kt = (ch + 1) * 32;
#pragma unroll
            for (int i = 0; i < 4; ++i) {
                int slot = i * 256 + tid;
                int row  = slot >> 3;
                int q    = (slot & 7) << 2;
                pa[i] = *(const float4*)(A + (size_t)(m0 + row) * DMODEL + kt + q);
                pw[i] = *(const float4*)(W + (size_t)(n0 + row) * DMODEL + kt + q);
            }
        }

        const uint32_t bufb = sb + (uint32_t)((ch & 1) * F16BUF_SZ);
        const uint32_t aBase = bufb + (uint32_t)(wm * 64) * PITCH_B + laneOff;
        const uint32_t wBase = bufb + (uint32_t)(wn * 32) * PITCH_B + laneOff;

#pragma unroll
        for (int ks = 0; ks < 2; ++ks) {
            const uint32_t so = (uint32_t)ks * SL_SZ;
            uint32_t ah[4][4], wh[2][4];
#pragma unroll
            for (int mt = 0; mt < 4; ++mt)
                LDSM_X4(ah[mt][0], ah[mt][1], ah[mt][2], ah[mt][3],
                        aBase + F16A_OFF + so + mt * 16 * PITCH_B);
#pragma unroll
            for (int n2 = 0; n2 < 2; ++n2)
                LDSM_X4(wh[n2][0], wh[n2][1], wh[n2][2], wh[n2][3],
                        wBase + F16W_OFF + so + n2 * 16 * PITCH_B);
#pragma unroll
            for (int mt = 0; mt < 4; ++mt)
#pragma unroll
                for (int nt = 0; nt < 4; ++nt)
                    MMA_FP16(acc[mt][nt], ah[mt],
                             wh[nt >> 1][nt & 1], wh[nt >> 1][(nt & 1) + 2]);
        }
    }

    const int group = lane >> 2;
    const int tcol  = (lane & 3) * 2;
#pragma unroll
    for (int mt = 0; mt < 4; ++mt) {
#pragma unroll
        for (int nt = 0; nt < 4; ++nt) {
            int row = m0 + wm * 64 + mt * 16 + group;
            int col = n0 + wn * 32 + nt * 8 + tcol;
            float bx = bias[col], by = bias[col + 1];
            *(float2*)(C + (size_t)row * DMODEL + col) =
                make_float2(acc[mt][nt][0] + bx, acc[mt][nt][1] + by);
            *(float2*)(C + (size_t)(row + 8) * DMODEL + col) =
                make_float2(acc[mt][nt][2] + bx, acc[mt][nt][3] + by);
        }
    }
}

// ======================= HMMA flash attention (all fp16 operands) ==========
#define APITCH    144
#define KF_OFF    0
#define VF_OFF    9216
#define KVBUF_SZ  18432
#define QF_OFF    36864
#define MASK_OFF  55296
#define ATTN_SMEM (MASK_OFF + 2 * 64 * 4)   // 55808

__global__ void __launch_bounds__(256, 2) attn_mma(
    const float* __restrict__ Q, const float* __restrict__ K,
    const float* __restrict__ V, const int* __restrict__ mask,
    float* __restrict__ ctx)
{
    extern __shared__ __align__(128) char smem[];
    const uint32_t sb = smem_u32(smem);
    const int tid  = threadIdx.x;
    const int lane = tid & 31;
    const int wid  = tid >> 5;
    const int q0   = blockIdx.x * 128;
    const int h    = blockIdx.y;
    const int b    = blockIdx.z;
    const size_t base = (size_t)(b * NHEADS + h) * S_LEN * DK;

    const uint32_t laneOff = (uint32_t)((lane & 15) * APITCH + (lane >> 4) * 16);

#pragma unroll
    for (int i = 0; i < 8; ++i) {
        int slot = i * 256 + tid;
        int row  = slot >> 4;
        int dq   = (slot & 15) << 2;
        float4 v = *(const float4*)(Q + base + (size_t)(q0 + row) * DK + dq);
        v.x *= 0.125f; v.y *= 0.125f; v.z *= 0.125f; v.w *= 0.125f;
        *(uint2*)(smem + QF_OFF + row * APITCH + dq * 2) = pack_f4(v);
    }

    float4 pk[4], pv[4];
#pragma unroll
    for (int i = 0; i < 4; ++i) {
        int slot = i * 256 + tid;
        int row  = slot >> 4;
        int dq   = (slot & 15) << 2;
        size_t goff = base + (size_t)row * DK + dq;
        pk[i] = *(const float4*)(K + goff);
        pv[i] = *(const float4*)(V + goff);
    }
    __syncthreads();

    uint32_t qf[4][4];
    {
        const uint32_t qB = sb + QF_OFF + (uint32_t)(wid * 16) * APITCH + laneOff;
#pragma unroll
        for (int s = 0; s < 4; ++s)
            LDSM_X4(qf[s][0], qf[s][1], qf[s][2], qf[s][3], qB + s * 32);
    }

    float o[8][4];
#pragma unroll
    for (int dt = 0; dt < 8; ++dt)
#pragma unroll
        for (int r = 0; r < 4; ++r) o[dt][r] = 0.0f;
    float mi0 = -1.0e30f, mi1 = -1.0e30f, li0 = 0.0f, li1 = 0.0f;

#pragma unroll 1
    for (int t = 0; t < 32; ++t) {
        const int buf = t & 1;
        char* sp = smem + buf * KVBUF_SZ;

#pragma unroll
        for (int i = 0; i < 4; ++i) {
            int slot = i * 256 + tid;
            int row  = slot >> 4;
            int dq   = (slot & 15) << 2;
            int soff = row * APITCH + dq * 2;
            *(uint2*)(sp + KF_OFF + soff) = pack_f4(pk[i]);
            *(uint2*)(sp + VF_OFF + soff) = pack_f4(pv[i]);
        }
        if (tid < 64)
            ((int*)(smem + MASK_OFF))[buf * 64 + tid] = mask[b * S_LEN + t * 64 + tid];
        __syncthreads();

        if (t + 1 < 32) {
            const int k1 = (t + 1) * 64;
#pragma unroll
            for (int i = 0; i < 4; ++i) {
                int slot = i * 256 + tid;
                int row  = slot >> 4;
                int dq   = (slot & 15) << 2;
                size_t goff = base + (size_t)(k1 + row) * DK + dq;
                pk[i] = *(const float4*)(K + goff);
                pv[i] = *(const float4*)(V + goff);
            }
        }

        float s_[8][4];
#pragma unroll
        for (int nt = 0; nt < 8; ++nt)
#pragma unroll
            for (int r = 0; r < 4; ++r) s_[nt][r] = 0.0f;

        const uint32_t kB = sb + (uint32_t)(buf * KVBUF_SZ) + laneOff;
#pragma unroll
        for (int st = 0; st < 4; ++st) {
#pragma unroll
            for (int g2 = 0; g2 < 4; ++g2) {
                uint32_t kf[4];
                LDSM_X4(kf[0], kf[1], kf[2], kf[3],
                        kB + KF_OFF + g2 * (16 * APITCH) + st * 32);
                MMA_FP16(s_[2 * g2],     qf[st], kf[0], kf[2]);
                MMA_FP16(s_[2 * g2 + 1], qf[st], kf[1], kf[3]);
            }
        }

        const int* mbuf = (const int*)(smem + MASK_OFF) + buf * 64;
#pragma unroll
        for (int nt = 0; nt < 8; ++nt) {
            int2 mv = *(const int2*)&mbuf[nt * 8 + (lane & 3) * 2];
            if (mv.x == 0) { s_[nt][0] = -1.0e9f; s_[nt][2] = -1.0e9f; }
            if (mv.y == 0) { s_[nt][1] = -1.0e9f; s_[nt][3] = -1.0e9f; }
        }

        float mx0 = -1.0e30f, mx1 = -1.0e30f;
#pragma unroll
        for (int nt = 0; nt < 8; ++nt) {
            mx0 = fmaxf(mx0, fmaxf(s_[nt][0], s_[nt][1]));
            mx1 = fmaxf(mx1, fmaxf(s_[nt][2], s_[nt][3]));
        }
        mx0 = fmaxf(mx0, __shfl_xor_sync(0xffffffffu, mx0, 1));
        mx0 = fmaxf(mx0, __shfl_xor_sync(0xffffffffu, mx0, 2));
        mx1 = fmaxf(mx1, __shfl_xor_sync(0xffffffffu, mx1, 1));
        mx1 = fmaxf(mx1, __shfl_xor_sync(0xffffffffu, mx1, 2));
        const float mn0 = fmaxf(mi0, mx0), mn1 = fmaxf(mi1, mx1);
        const float a0 = __expf(mi0 - mn0), a1 = __expf(mi1 - mn1);
        mi0 = mn0; mi1 = mn1;

        float sum0 = 0.0f, sum1 = 0.0f;
#pragma unroll
        for (int nt = 0; nt < 8; ++nt) {
            s_[nt][0] = __expf(s_[nt][0] - mn0);
            s_[nt][1] = __expf(s_[nt][1] - mn0);
            s_[nt][2] = __expf(s_[nt][2] - mn1);
            s_[nt][3] = __expf(s_[nt][3] - mn1);
            sum0 += s_[nt][0] + s_[nt][1];
            sum1 += s_[nt][2] + s_[nt][3];
        }
        sum0 += __shfl_xor_sync(0xffffffffu, sum0, 1);
        sum0 += __shfl_xor_sync(0xffffffffu, sum0, 2);
        sum1 += __shfl_xor_sync(0xffffffffu, sum1, 1);
        sum1 += __shfl_xor_sync(0xffffffffu, sum1, 2);
        li0 = li0 * a0 + sum0;
        li1 = li1 * a1 + sum1;

#pragma unroll
        for (int dt = 0; dt < 8; ++dt) {
            o[dt][0] *= a0; o[dt][1] *= a0;
            o[dt][2] *= a1; o[dt][3] *= a1;
        }

        const uint32_t vB = sb + (uint32_t)(buf * KVBUF_SZ) + laneOff;
#pragma unroll
        for (int st = 0; st < 4; ++st) {
            uint32_t pf[4];
            pf[0] = pack_f16(s_[2 * st][0],     s_[2 * st][1]);
            pf[1] = pack_f16(s_[2 * st][2],     s_[2 * st][3]);
            pf[2] = pack_f16(s_[2 * st + 1][0], s_[2 * st + 1][1]);
            pf[3] = pack_f16(s_[2 * st + 1][2], s_[2 * st + 1][3]);
#pragma unroll
            for (int j = 0; j < 4; ++j) {
                uint32_t vf[4];
                LDSM_X4_T(vf[0], vf[1], vf[2], vf[3],
                          vB + VF_OFF + st * (16 * APITCH) + j * 32);
                MMA_FP16(o[2 * j],     pf, vf[0], vf[1]);
                MMA_FP16(o[2 * j + 1], pf, vf[2], vf[3]);
            }
        }
    }

    const int g  = lane >> 2;
    const int t2 = (lane & 3) * 2;
    const int row0 = q0 + wid * 16 + g;
    const int row1 = row0 + 8;
    const float inv0 = 1.0f / li0, inv1 = 1.0f / li1;
#pragma unroll
    for (int dt = 0; dt < 8; ++dt) {
        int col = h * DK + dt * 8 + t2;
        *(float2*)(ctx + (size_t)(b * S_LEN + row0) * DMODEL + col) =
            make_float2(o[dt][0] * inv0, o[dt][1] * inv0);
        *(float2*)(ctx + (size_t)(b * S_LEN + row1) * DMODEL + col) =
            make_float2(o[dt][2] * inv1, o[dt][3] * inv1);
    }
}

// ---------------------------------------------------------------------------
extern "C" void kernel_launch(void* const* d_in, const int* in_sizes, int n_in,
                              void* d_out, int out_size)
{
    const float* query = (const float*)d_in[0];
    const float* key   = (const float*)d_in[1];
    const float* value = (const float*)d_in[2];
    const int*   mask  = (const int*)d_in[3];
    const float* Wq = (const float*)d_in[4];
    const float* bq = (const float*)d_in[5];
    const float* Wk = (const float*)d_in[6];
    const float* bk = (const float*)d_in[7];
    const float* Wv = (const float*)d_in[8];
    const float* bv = (const float*)d_in[9];
    const float* Wo = (const float*)d_in[10];
    const float* bo = (const float*)d_in[11];
    float* out = (float*)d_out;

    float *Qd, *Kd, *Vd, *Cd;
    cudaGetSymbolAddress((void**)&Qd, g_Q);
    cudaGetSymbolAddress((void**)&Kd, g_K);
    cudaGetSymbolAddress((void**)&Vd, g_V);
    cudaGetSymbolAddress((void**)&Cd, g_ctx);

    cudaFuncSetAttribute(gemm_qkv, cudaFuncAttributeMaxDynamicSharedMemorySize, QKV_SMEM);
    cudaFuncSetAttribute(gemm_out_f16, cudaFuncAttributeMaxDynamicSharedMemorySize, OUT_SMEM);
    cudaFuncSetAttribute(attn_mma, cudaFuncAttributeMaxDynamicSharedMemorySize, ATTN_SMEM);

    dim3 gq(DMODEL / 128, MTOT / 128, 3);       // (8, 32, 3) = 768 CTAs
    gemm_qkv<<<gq, 256, QKV_SMEM>>>(query, key, value, Wq, Wk, Wv,
                                    bq, bk, bv, Qd, Kd, Vd);

    dim3 ag(S_LEN / 128, NHEADS, BATCH);        // (16, 16, 2) = 512 CTAs
    attn_mma<<<ag, 256, ATTN_SMEM>>>(Qd, Kd, Vd, mask, Cd);

    dim3 gg(DMODEL / 128, MTOT / 128);          // (8, 32) = 256 CTAs
    gemm_out_f16<<<gg, 256, OUT_SMEM>>>(Cd, Wo, bo, out);
}

// round 11
// speedup vs baseline: 2.1349x; 1.1182x over previous
#include <cuda_runtime.h>
#include <cuda_bf16.h>
#include <cuda_fp16.h>
#include <cstdint>

#define S_LEN   2048
#define BATCH   2
#define DMODEL  1024
#define NHEADS  16
#define DK      64
#define MTOT    (BATCH * S_LEN)   // 4096

// ---------------- scratch (static device globals; no dynamic allocation) ----
__device__ float g_Q[BATCH * NHEADS * S_LEN * DK];    // (b,h,s,d)
__device__ float g_K[BATCH * NHEADS * S_LEN * DK];
__device__ float g_V[BATCH * NHEADS * S_LEN * DK];
__device__ float g_ctx[MTOT * DMODEL];                // (b,s,h*d)

// ======================= warp-MMA helpers (portable PTX) ====================
__device__ __forceinline__ uint32_t smem_u32(const void* p) {
    uint32_t a;
    asm("{ .reg .u64 t; cvta.to.shared.u64 t, %1; cvt.u32.u64 %0, t; }"
        : "=r"(a) : "l"(p));
    return a;
}

#define LDSM_X4(r0, r1, r2, r3, addr) \
    asm volatile("ldmatrix.sync.aligned.m8n8.x4.shared.b16 {%0,%1,%2,%3}, [%4];" \
                 : "=r"(r0), "=r"(r1), "=r"(r2), "=r"(r3) : "r"(addr))

#define LDSM_X4_T(r0, r1, r2, r3, addr) \
    asm volatile("ldmatrix.sync.aligned.m8n8.x4.trans.shared.b16 {%0,%1,%2,%3}, [%4];" \
                 : "=r"(r0), "=r"(r1), "=r"(r2), "=r"(r3) : "r"(addr))

#define MMA_FP16(d, a, b0, b1) \
    asm volatile("mma.sync.aligned.m16n8k16.row.col.f32.f16.f16.f32 " \
                 "{%0,%1,%2,%3}, {%4,%5,%6,%7}, {%8,%9}, {%0,%1,%2,%3};" \
                 : "+f"((d)[0]), "+f"((d)[1]), "+f"((d)[2]), "+f"((d)[3]) \
                 : "r"((a)[0]), "r"((a)[1]), "r"((a)[2]), "r"((a)[3]), \
                   "r"(b0), "r"(b1))

__device__ __forceinline__ uint32_t pack_f16(float a, float b) {   // low = a
    uint32_t r;
    asm("cvt.rn.f16x2.f32 %0, %1, %2;" : "=r"(r) : "f"(b), "f"(a));
    return r;
}
__device__ __forceinline__ uint2 pack_f4(float4 v) {
    return make_uint2(pack_f16(v.x, v.y), pack_f16(v.z, v.w));
}

// ======================= single-term fp16 GEMM body ========================
// C[4096,1024] = A @ W^T + bias, both operands fp16, fp32 accumulate.
// MODE 0: row-major fp32 out.  MODE 1: head-major (b,h,s,d) fp32 out.
#define PITCH_B   48
#define SL_SZ     6144
#define F16A_OFF  0
#define F16W_OFF  12288
#define F16BUF_SZ 24576
#define GEMM_SMEM (2 * F16BUF_SZ)   // 49152

template <int MODE>
__device__ __forceinline__ void gemm_body_f16(
    const float* __restrict__ A, const float* __restrict__ W,
    const float* __restrict__ bias, float* __restrict__ C, char* smem)
{
    const uint32_t sb = smem_u32(smem);
    const int tid  = threadIdx.x;
    const int lane = tid & 31;
    const int wid  = tid >> 5;
    const int wm   = wid >> 2;
    const int wn   = wid & 3;
    const int m0   = blockIdx.y * 128;
    const int n0   = blockIdx.x * 128;

    const uint32_t laneOff = (uint32_t)((lane & 15) * PITCH_B + (lane >> 4) * 16);

    float acc[4][4][4];
#pragma unroll
    for (int i = 0; i < 4; ++i)
#pragma unroll
        for (int j = 0; j < 4; ++j)
#pragma unroll
            for (int r = 0; r < 4; ++r) acc[i][j][r] = 0.0f;

    float4 pa[4], pw[4];
#pragma unroll
    for (int i = 0; i < 4; ++i) {
        int slot = i * 256 + tid;
        int row  = slot >> 3;
        int q    = (slot & 7) << 2;
        pa[i] = *(const float4*)(A + (size_t)(m0 + row) * DMODEL + q);
        pw[i] = *(const float4*)(W + (size_t)(n0 + row) * DMODEL + q);
    }

#pragma unroll 1
    for (int ch = 0; ch < 32; ++ch) {
        char* sp = smem + (ch & 1) * F16BUF_SZ;

#pragma unroll
        for (int i = 0; i < 4; ++i) {
            int slot = i * 256 + tid;
            int row  = slot >> 3;
            int q    = (slot & 7) << 2;
            int soff = (q >> 4) * SL_SZ + row * PITCH_B + (q & 15) * 2;
            *(uint2*)(sp + F16A_OFF + soff) = pack_f4(pa[i]);
            *(uint2*)(sp + F16W_OFF + soff) = pack_f4(pw[i]);
        }
        __syncthreads();

        if (ch + 1 < 32) {
            const int kt = (ch + 1) * 32;
#pragma unroll
            for (int i = 0; i < 4; ++i) {
                int slot = i * 256 + tid;
                int row  = slot >> 3;
                int q    = (slot & 7) << 2;
                pa[i] = *(const float4*)(A + (size_t)(m0 + row) * DMODEL + kt + q);
                pw[i] = *(const float4*)(W + (size_t)(n0 + row) * DMODEL + kt + q);
            }
        }

        const uint32_t bufb = sb + (uint32_t)((ch & 1) * F16BUF_SZ);
        const uint32_t aBase = bufb + (uint32_t)(wm * 64) * PITCH_B + laneOff;
        const uint32_t wBase = bufb + (uint32_t)(wn * 32) * PITCH_B + laneOff;

#pragma unroll
        for (int ks = 0; ks < 2; ++ks) {
            const uint32_t so = (uint32_t)ks * SL_SZ;
            uint32_t ah[4][4], wh[2][4];
#pragma unroll
            for (int mt = 0; mt < 4; ++mt)
                LDSM_X4(ah[mt][0], ah[mt][1], ah[mt][2], ah[mt][3],
                        aBase + F16A_OFF + so + mt * 16 * PITCH_B);
#pragma unroll
            for (int n2 = 0; n2 < 2; ++n2)
                LDSM_X4(wh[n2][0], wh[n2][1], wh[n2][2], wh[n2][3],
                        wBase + F16W_OFF + so + n2 * 16 * PITCH_B);
#pragma unroll
            for (int mt = 0; mt < 4; ++mt)
#pragma unroll
                for (int nt = 0; nt < 4; ++nt)
                    MMA_FP16(acc[mt][nt], ah[mt],
                             wh[nt >> 1][nt & 1], wh[nt >> 1][(nt & 1) + 2]);
        }
    }

    const int group = lane >> 2;
    const int tcol  = (lane & 3) * 2;
#pragma unroll
    for (int mt = 0; mt < 4; ++mt) {
#pragma unroll
        for (int nt = 0; nt < 4; ++nt) {
            int row = m0 + wm * 64 + mt * 16 + group;
            int col = n0 + wn * 32 + nt * 8 + tcol;
            float bx = bias[col], by = bias[col + 1];
            float2 v0 = make_float2(acc[mt][nt][0] + bx, acc[mt][nt][1] + by);
            float2 v1 = make_float2(acc[mt][nt][2] + bx, acc[mt][nt][3] + by);
            if (MODE == 0) {
                *(float2*)(C + (size_t)row * DMODEL + col) = v0;
                *(float2*)(C + (size_t)(row + 8) * DMODEL + col) = v1;
            } else {
                int h = col >> 6, d = col & 63;
                int b0_ = row >> 11, s0_ = row & 2047;
                int b1_ = (row + 8) >> 11, s1_ = (row + 8) & 2047;
                *(float2*)(C + (((size_t)(b0_ * NHEADS + h) * S_LEN + s0_) * DK) + d) = v0;
                *(float2*)(C + (((size_t)(b1_ * NHEADS + h) * S_LEN + s1_) * DK) + d) = v1;
            }
        }
    }
}

// fused Q/K/V projection: blockIdx.z selects input/weight/bias/output
__global__ void __launch_bounds__(256, 2) gemm_qkv(
    const float* __restrict__ q, const float* __restrict__ k,
    const float* __restrict__ v,
    const float* __restrict__ Wq, const float* __restrict__ Wk,
    const float* __restrict__ Wv,
    const float* __restrict__ bq, const float* __restrict__ bk,
    const float* __restrict__ bv,
    float* __restrict__ Qd, float* __restrict__ Kd, float* __restrict__ Vd)
{
    extern __shared__ __align__(128) char smem[];
    const float *A, *W, *bias;
    float* C;
    if (blockIdx.z == 0)      { A = q; W = Wq; bias = bq; C = Qd; }
    else if (blockIdx.z == 1) { A = k; W = Wk; bias = bk; C = Kd; }
    else                      { A = v; W = Wv; bias = bv; C = Vd; }
    gemm_body_f16<1>(A, W, bias, C, smem);
}

__global__ void __launch_bounds__(256, 2) gemm_out_f16(
    const float* __restrict__ A, const float* __restrict__ W,
    const float* __restrict__ bias, float* __restrict__ C)
{
    extern __shared__ __align__(128) char smem[];
    gemm_body_f16<0>(A, W, bias, C, smem);
}

// ======================= HMMA flash attention (all fp16 operands) ==========
#define APITCH    144
#define KF_OFF    0
#define VF_OFF    9216
#define KVBUF_SZ  18432
#define QF_OFF    36864
#define MASK_OFF  55296
#define ATTN_SMEM (MASK_OFF + 2 * 64 * 4)   // 55808

__global__ void __launch_bounds__(256, 2) attn_mma(
    const float* __restrict__ Q, const float* __restrict__ K,
    const float* __restrict__ V, const int* __restrict__ mask,
    float* __restrict__ ctx)
{
    extern __shared__ __align__(128) char smem[];
    const uint32_t sb = smem_u32(smem);
    const int tid  = threadIdx.x;
    const int lane = tid & 31;
    const int wid  = tid >> 5;
    const int q0   = blockIdx.x * 128;
    const int h    = blockIdx.y;
    const int b    = blockIdx.z;
    const size_t base = (size_t)(b * NHEADS + h) * S_LEN * DK;

    const uint32_t laneOff = (uint32_t)((lane & 15) * APITCH + (lane >> 4) * 16);

#pragma unroll
    for (int i = 0; i < 8; ++i) {
        int slot = i * 256 + tid;
        int row  = slot >> 4;
        int dq   = (slot & 15) << 2;
        float4 v = *(const float4*)(Q + base + (size_t)(q0 + row) * DK + dq);
        v.x *= 0.125f; v.y *= 0.125f; v.z *= 0.125f; v.w *= 0.125f;
        *(uint2*)(smem + QF_OFF + row * APITCH + dq * 2) = pack_f4(v);
    }

    float4 pk[4], pv[4];
#pragma unroll
    for (int i = 0; i < 4; ++i) {
        int slot = i * 256 + tid;
        int row  = slot >> 4;
        int dq   = (slot & 15) << 2;
        size_t goff = base + (size_t)row * DK + dq;
        pk[i] = *(const float4*)(K + goff);
        pv[i] = *(const float4*)(V + goff);
    }
    __syncthreads();

    uint32_t qf[4][4];
    {
        const uint32_t qB = sb + QF_OFF + (uint32_t)(wid * 16) * APITCH + laneOff;
#pragma unroll
        for (int s = 0; s < 4; ++s)
            LDSM_X4(qf[s][0], qf[s][1], qf[s][2], qf[s][3], qB + s * 32);
    }

    float o[8][4];
#pragma unroll
    for (int dt = 0; dt < 8; ++dt)
#pragma unroll
        for (int r = 0; r < 4; ++r) o[dt][r] = 0.0f;
    float mi0 = -1.0e30f, mi1 = -1.0e30f, li0 = 0.0f, li1 = 0.0f;

#pragma unroll 1
    for (int t = 0; t < 32; ++t) {
        const int buf = t & 1;
        char* sp = smem + buf * KVBUF_SZ;

#pragma unroll
        for (int i = 0; i < 4; ++i) {
            int slot = i * 256 + tid;
            int row  = slot >> 4;
            int dq   = (slot & 15) << 2;
            int soff = row * APITCH + dq * 2;
            *(uint2*)(sp + KF_OFF + soff) = pack_f4(pk[i]);
            *(uint2*)(sp + VF_OFF + soff) = pack_f4(pv[i]);
        }
        if (tid < 64)
            ((int*)(smem + MASK_OFF))[buf * 64 + tid] = mask[b * S_LEN + t * 64 + tid];
        __syncthreads();

        if (t + 1 < 32) {
            const int k1 = (t + 1) * 64;
#pragma unroll
            for (int i = 0; i < 4; ++i) {
                int slot = i * 256 + tid;
                int row  = slot >> 4;
                int dq   = (slot & 15) << 2;
                size_t goff = base + (size_t)(k1 + row) * DK + dq;
                pk[i] = *(const float4*)(K + goff);
                pv[i] = *(const float4*)(V + goff);
            }
        }

        float s_[8][4];
#pragma unroll
        for (int nt = 0; nt < 8; ++nt)
#pragma unroll
            for (int r = 0; r < 4; ++r) s_[nt][r] = 0.0f;

        const uint32_t kB = sb + (uint32_t)(buf * KVBUF_SZ) + laneOff;
#pragma unroll
        for (int st = 0; st < 4; ++st) {
#pragma unroll
            for (int g2 = 0; g2 < 4; ++g2) {
                uint32_t kf[4];
                LDSM_X4(kf[0], kf[1], kf[2], kf[3],
                        kB + KF_OFF + g2 * (16 * APITCH) + st * 32);
                MMA_FP16(s_[2 * g2],     qf[st], kf[0], kf[2]);
                MMA_FP16(s_[2 * g2 + 1], qf[st], kf[1], kf[3]);
            }
        }

        const int* mbuf = (const int*)(smem + MASK_OFF) + buf * 64;
#pragma unroll
        for (int nt = 0; nt < 8; ++nt) {
            int2 mv = *(const int2*)&mbuf[nt * 8 + (lane & 3) * 2];
            if (mv.x == 0) { s_[nt][0] = -1.0e9f; s_[nt][2] = -1.0e9f; }
            if (mv.y == 0) { s_[nt][1] = -1.0e9f; s_[nt][3] = -1.0e9f; }
        }

        float mx0 = -1.0e30f, mx1 = -1.0e30f;
#pragma unroll
        for (int nt = 0; nt < 8; ++nt) {
            mx0 = fmaxf(mx0, fmaxf(s_[nt][0], s_[nt][1]));
            mx1 = fmaxf(mx1, fmaxf(s_[nt][2], s_[nt][3]));
        }
        mx0 = fmaxf(mx0, __shfl_xor_sync(0xffffffffu, mx0, 1));
        mx0 = fmaxf(mx0, __shfl_xor_sync(0xffffffffu, mx0, 2));
        mx1 = fmaxf(mx1, __shfl_xor_sync(0xffffffffu, mx1, 1));
        mx1 = fmaxf(mx1, __shfl_xor_sync(0xffffffffu, mx1, 2));
        const float mn0 = fmaxf(mi0, mx0), mn1 = fmaxf(mi1, mx1);
        const float a0 = __expf(mi0 - mn0), a1 = __expf(mi1 - mn1);
        mi0 = mn0; mi1 = mn1;

        float sum0 = 0.0f, sum1 = 0.0f;
#pragma unroll
        for (int nt = 0; nt < 8; ++nt) {
            s_[nt][0] = __expf(s_[nt][0] - mn0);
            s_[nt][1] = __expf(s_[nt][1] - mn0);
            s_[nt][2] = __expf(s_[nt][2] - mn1);
            s_[nt][3] = __expf(s_[nt][3] - mn1);
            sum0 += s_[nt][0] + s_[nt][1];
            sum1 += s_[nt][2] + s_[nt][3];
        }
        sum0 += __shfl_xor_sync(0xffffffffu, sum0, 1);
        sum0 += __shfl_xor_sync(0xffffffffu, sum0, 2);
        sum1 += __shfl_xor_sync(0xffffffffu, sum1, 1);
        sum1 += __shfl_xor_sync(0xffffffffu, sum1, 2);
        li0 = li0 * a0 + sum0;
        li1 = li1 * a1 + sum1;

#pragma unroll
        for (int dt = 0; dt < 8; ++dt) {
            o[dt][0] *= a0; o[dt][1] *= a0;
            o[dt][2] *= a1; o[dt][3] *= a1;
        }

        const uint32_t vB = sb + (uint32_t)(buf * KVBUF_SZ) + laneOff;
#pragma unroll
        for (int st = 0; st < 4; ++st) {
            uint32_t pf[4];
            pf[0] = pack_f16(s_[2 * st][0],     s_[2 * st][1]);
            pf[1] = pack_f16(s_[2 * st][2],     s_[2 * st][3]);
            pf[2] = pack_f16(s_[2 * st + 1][0], s_[2 * st + 1][1]);
            pf[3] = pack_f16(s_[2 * st + 1][2], s_[2 * st + 1][3]);
#pragma unroll
            for (int j = 0; j < 4; ++j) {
                uint32_t vf[4];
                LDSM_X4_T(vf[0], vf[1], vf[2], vf[3],
                          vB + VF_OFF + st * (16 * APITCH) + j * 32);
                MMA_FP16(o[2 * j],     pf, vf[0], vf[1]);
                MMA_FP16(o[2 * j + 1], pf, vf[2], vf[3]);
            }
        }
    }

    const int g  = lane >> 2;
    const int t2 = (lane & 3) * 2;
    const int row0 = q0 + wid * 16 + g;
    const int row1 = row0 + 8;
    const float inv0 = 1.0f / li0, inv1 = 1.0f / li1;
#pragma unroll
    for (int dt = 0; dt < 8; ++dt) {
        int col = h * DK + dt * 8 + t2;
        *(float2*)(ctx + (size_t)(b * S_LEN + row0) * DMODEL + col) =
            make_float2(o[dt][0] * inv0, o[dt][1] * inv0);
        *(float2*)(ctx + (size_t)(b * S_LEN + row1) * DMODEL + col) =
            make_float2(o[dt][2] * inv1, o[dt][3] * inv1);
    }
}

// ---------------------------------------------------------------------------
extern "C" void kernel_launch(void* const* d_in, const int* in_sizes, int n_in,
                              void* d_out, int out_size)
{
    const float* query = (const float*)d_in[0];
    const float* key   = (const float*)d_in[1];
    const float* value = (const float*)d_in[2];
    const int*   mask  = (const int*)d_in[3];
    const float* Wq = (const float*)d_in[4];
    const float* bq = (const float*)d_in[5];
    const float* Wk = (const float*)d_in[6];
    const float* bk = (const float*)d_in[7];
    const float* Wv = (const float*)d_in[8];
    const float* bv = (const float*)d_in[9];
    const float* Wo = (const float*)d_in[10];
    const float* bo = (const float*)d_in[11];
    float* out = (float*)d_out;

    float *Qd, *Kd, *Vd, *Cd;
    cudaGetSymbolAddress((void**)&Qd, g_Q);
    cudaGetSymbolAddress((void**)&Kd, g_K);
    cudaGetSymbolAddress((void**)&Vd, g_V);
    cudaGetSymbolAddress((void**)&Cd, g_ctx);

    cudaFuncSetAttribute(gemm_qkv, cudaFuncAttributeMaxDynamicSharedMemorySize, GEMM_SMEM);
    cudaFuncSetAttribute(gemm_out_f16, cudaFuncAttributeMaxDynamicSharedMemorySize, GEMM_SMEM);
    cudaFuncSetAttribute(attn_mma, cudaFuncAttributeMaxDynamicSharedMemorySize, ATTN_SMEM);

    dim3 gq(DMODEL / 128, MTOT / 128, 3);       // (8, 32, 3) = 768 CTAs
    gemm_qkv<<<gq, 256, GEMM_SMEM>>>(query, key, value, Wq, Wk, Wv,
                                     bq, bk, bv, Qd, Kd, Vd);

    dim3 ag(S_LEN / 128, NHEADS, BATCH);        // (16, 16, 2) = 512 CTAs
    attn_mma<<<ag, 256, ATTN_SMEM>>>(Qd, Kd, Vd, mask, Cd);

    dim3 gg(DMODEL / 128, MTOT / 128);          // (8, 32) = 256 CTAs
    gemm_out_f16<<<gg, 256, GEMM_SMEM>>>(Cd, Wo, bo, out);
}

// round 12
// speedup vs baseline: 2.1754x; 1.0190x over previous
#include <cuda_runtime.h>
#include <cuda_fp16.h>
#include <cstdint>

#define S_LEN   2048
#define BATCH   2
#define DMODEL  1024
#define NHEADS  16
#define DK      64
#define MTOT    (BATCH * S_LEN)   // 4096

// ---------------- scratch (static device globals; no dynamic allocation) ----
__device__ __half g_xf[3][(size_t)MTOT * DMODEL];     // fp16 query,key,value
__device__ __half g_wf[4][(size_t)DMODEL * DMODEL];   // fp16 Wq,Wk,Wv,Wo
__device__ __half g_qkv[3][(size_t)MTOT * DMODEL];    // fp16 Q,K,V (b,h,s,d); Q pre-scaled
__device__ __half g_ctx[(size_t)MTOT * DMODEL];       // fp16 ctx (b,s,h*d)

// ======================= PTX helpers =======================================
__device__ __forceinline__ uint32_t smem_u32(const void* p) {
    uint32_t a;
    asm("{ .reg .u64 t; cvta.to.shared.u64 t, %1; cvt.u32.u64 %0, t; }"
        : "=r"(a) : "l"(p));
    return a;
}

#define LDSM_X4(r0, r1, r2, r3, addr) \
    asm volatile("ldmatrix.sync.aligned.m8n8.x4.shared.b16 {%0,%1,%2,%3}, [%4];" \
                 : "=r"(r0), "=r"(r1), "=r"(r2), "=r"(r3) : "r"(addr))

#define LDSM_X4_T(r0, r1, r2, r3, addr) \
    asm volatile("ldmatrix.sync.aligned.m8n8.x4.trans.shared.b16 {%0,%1,%2,%3}, [%4];" \
                 : "=r"(r0), "=r"(r1), "=r"(r2), "=r"(r3) : "r"(addr))

#define MMA_FP16(d, a, b0, b1) \
    asm volatile("mma.sync.aligned.m16n8k16.row.col.f32.f16.f16.f32 " \
                 "{%0,%1,%2,%3}, {%4,%5,%6,%7}, {%8,%9}, {%0,%1,%2,%3};" \
                 : "+f"((d)[0]), "+f"((d)[1]), "+f"((d)[2]), "+f"((d)[3]) \
                 : "r"((a)[0]), "r"((a)[1]), "r"((a)[2]), "r"((a)[3]), \
                   "r"(b0), "r"(b1))

#define CPA16(saddr, gptr) \
    asm volatile("cp.async.ca.shared.global [%0], [%1], 16;" \
                 :: "r"(saddr), "l"(gptr))
#define CP_COMMIT() asm volatile("cp.async.commit_group;" ::: "memory")
#define CP_WAIT0()  asm volatile("cp.async.wait_group 0;" ::: "memory")
#define CP_WAIT1()  asm volatile("cp.async.wait_group 1;" ::: "memory")
#define CP_WAIT2()  asm volatile("cp.async.wait_group 2;" ::: "memory")

__device__ __forceinline__ uint32_t pack_f16(float a, float b) {   // low = a
    uint32_t r;
    asm("cvt.rn.f16x2.f32 %0, %1, %2;" : "=r"(r) : "f"(b), "f"(a));
    return r;
}

// ======================= prep: fp32 -> fp16 (one pass) =====================
__global__ void __launch_bounds__(256) prep_f16(
    const float* __restrict__ q, const float* __restrict__ k,
    const float* __restrict__ v,
    const float* __restrict__ Wq, const float* __restrict__ Wk,
    const float* __restrict__ Wv, const float* __restrict__ Wo)
{
    const int z = blockIdx.y;
    const float* srcs[7] = {q, k, v, Wq, Wk, Wv, Wo};
    __half* dsts[7] = {g_xf[0], g_xf[1], g_xf[2],
                       g_wf[0], g_wf[1], g_wf[2], g_wf[3]};
    const int n4 = (z < 3) ? (MTOT * DMODEL / 4) : (DMODEL * DMODEL / 4);
    int i = blockIdx.x * 256 + threadIdx.x;
    if (i < n4) {
        float4 val = ((const float4*)srcs[z])[i];
        ((uint2*)dsts[z])[i] =
            make_uint2(pack_f16(val.x, val.y), pack_f16(val.z, val.w));
    }
}

// ======================= fp16 GEMM, 4-stage cp.async =======================
// C = A @ W^T + bias.  A,W fp16 row-major [.,1024].  fp32 accumulate.
// MODE 0: fp32 row-major out.  MODE 1: fp16 head-major out, * scale.
#define PITCH_B   48
#define SL_SZ     6144
#define STAGE_SZ  24576           // A 12288 + W 12288
#define GW_OFF    12288
#define GEMM_SMEM (4 * STAGE_SZ)  // 98304

template <int MODE>
__device__ __forceinline__ void gemm_body_f16(
    const __half* __restrict__ A, const __half* __restrict__ W,
    const float* __restrict__ bias, float* __restrict__ Cf,
    __half* __restrict__ Ch, float scale, char* smem)
{
    const uint32_t sb = smem_u32(smem);
    const int tid  = threadIdx.x;
    const int lane = tid & 31;
    const int wid  = tid >> 5;
    const int wm   = wid >> 2;
    const int wn   = wid & 3;
    const int m0   = blockIdx.y * 128;
    const int n0   = blockIdx.x * 128;

    const uint32_t laneOff = (uint32_t)((lane & 15) * PITCH_B + (lane >> 4) * 16);

    float acc[4][4][4];
#pragma unroll
    for (int i = 0; i < 4; ++i)
#pragma unroll
        for (int j = 0; j < 4; ++j)
#pragma unroll
            for (int r = 0; r < 4; ++r) acc[i][j][r] = 0.0f;

    auto issue = [&](int ch) {
        const uint32_t sbuf = sb + (uint32_t)((ch & 3) * STAGE_SZ);
        const int kt = ch * 32;
#pragma unroll
        for (int i = 0; i < 2; ++i) {
            int slot = i * 256 + tid;           // 0..511
            int row  = slot >> 2;               // 0..127
            int j    = slot & 3;                // 8-half group
            uint32_t soff = (uint32_t)((j >> 1) * SL_SZ + row * PITCH_B + (j & 1) * 16);
            CPA16(sbuf + soff,          A + (size_t)(m0 + row) * DMODEL + kt + j * 8);
            CPA16(sbuf + GW_OFF + soff, W + (size_t)(n0 + row) * DMODEL + kt + j * 8);
        }
        CP_COMMIT();
    };

    issue(0); issue(1); issue(2);

#pragma unroll 1
    for (int ch = 0; ch < 32; ++ch) {
        if (ch < 30)      CP_WAIT2();
        else if (ch == 30) CP_WAIT1();
        else               CP_WAIT0();
        __syncthreads();
        if (ch + 3 < 32) issue(ch + 3);

        const uint32_t bufb = sb + (uint32_t)((ch & 3) * STAGE_SZ);
        const uint32_t aBase = bufb + (uint32_t)(wm * 64) * PITCH_B + laneOff;
        const uint32_t wBase = bufb + GW_OFF + (uint32_t)(wn * 32) * PITCH_B + laneOff;

#pragma unroll
        for (int ks = 0; ks < 2; ++ks) {
            const uint32_t so = (uint32_t)ks * SL_SZ;
            uint32_t ah[4][4], wh[2][4];
#pragma unroll
            for (int mt = 0; mt < 4; ++mt)
                LDSM_X4(ah[mt][0], ah[mt][1], ah[mt][2], ah[mt][3],
                        aBase + so + mt * 16 * PITCH_B);
#pragma unroll
            for (int n2 = 0; n2 < 2; ++n2)
                LDSM_X4(wh[n2][0], wh[n2][1], wh[n2][2], wh[n2][3],
                        wBase + so + n2 * 16 * PITCH_B);
#pragma unroll
            for (int mt = 0; mt < 4; ++mt)
#pragma unroll
                for (int nt = 0; nt < 4; ++nt)
                    MMA_FP16(acc[mt][nt], ah[mt],
                             wh[nt >> 1][nt & 1], wh[nt >> 1][(nt & 1) + 2]);
        }
    }

    const int group = lane >> 2;
    const int tcol  = (lane & 3) * 2;
#pragma unroll
    for (int mt = 0; mt < 4; ++mt) {
#pragma unroll
        for (int nt = 0; nt < 4; ++nt) {
            int row = m0 + wm * 64 + mt * 16 + group;
            int col = n0 + wn * 32 + nt * 8 + tcol;
            float bx = bias[col], by = bias[col + 1];
            float v00 = acc[mt][nt][0] + bx, v01 = acc[mt][nt][1] + by;
            float v10 = acc[mt][nt][2] + bx, v11 = acc[mt][nt][3] + by;
            if (MODE == 0) {
                *(float2*)(Cf + (size_t)row * DMODEL + col) = make_float2(v00, v01);
                *(float2*)(Cf + (size_t)(row + 8) * DMODEL + col) = make_float2(v10, v11);
            } else {
                v00 *= scale; v01 *= scale; v10 *= scale; v11 *= scale;
                int h = col >> 6, d = col & 63;
                int b0_ = row >> 11, s0_ = row & 2047;
                int b1_ = (row + 8) >> 11, s1_ = (row + 8) & 2047;
                *(uint32_t*)(Ch + (((size_t)(b0_ * NHEADS + h) * S_LEN + s0_) * DK) + d)
                    = pack_f16(v00, v01);
                *(uint32_t*)(Ch + (((size_t)(b1_ * NHEADS + h) * S_LEN + s1_) * DK) + d)
                    = pack_f16(v10, v11);
            }
        }
    }
}

__global__ void __launch_bounds__(256, 2) gemm_qkv(
    const float* __restrict__ bq, const float* __restrict__ bk,
    const float* __restrict__ bv)
{
    extern __shared__ __align__(128) char smem[];
    const int z = blockIdx.z;
    const float* bias = (z == 0) ? bq : (z == 1) ? bk : bv;
    const float scale = (z == 0) ? 0.125f : 1.0f;
    gemm_body_f16<1>(g_xf[z], g_wf[z], bias, nullptr, g_qkv[z], scale, smem);
}

__global__ void __launch_bounds__(256, 2) gemm_out(
    const float* __restrict__ bias, float* __restrict__ C)
{
    extern __shared__ __align__(128) char smem[];
    gemm_body_f16<0>(g_ctx, g_wf[3], bias, C, nullptr, 1.0f, smem);
}

// ======================= flash attention, fp16 in/out, 3-stage cp.async ====
#define APITCH    144
#define KV_STAGE  18432           // K 9216 + V 9216
#define AV_OFF    9216
#define QF_OFF    55296           // 3 * KV_STAGE
#define MASK_OFF  73728
#define ATTN_SMEM (MASK_OFF + 2 * 64 * 4)   // 74240

__global__ void __launch_bounds__(256, 2) attn_mma(
    const int* __restrict__ mask)
{
    extern __shared__ __align__(128) char smem[];
    const __half* Q = g_qkv[0];
    const __half* K = g_qkv[1];
    const __half* V = g_qkv[2];
    const uint32_t sb = smem_u32(smem);
    const int tid  = threadIdx.x;
    const int lane = tid & 31;
    const int wid  = tid >> 5;
    const int q0   = blockIdx.x * 128;
    const int h    = blockIdx.y;
    const int b    = blockIdx.z;
    const size_t base = (size_t)(b * NHEADS + h) * S_LEN * DK;

    const uint32_t laneOff = (uint32_t)((lane & 15) * APITCH + (lane >> 4) * 16);

    auto issue_kv = [&](int t) {
        int st = t % 3;
        const uint32_t sp = sb + (uint32_t)(st * KV_STAGE);
        const int k0 = t * 64;
#pragma unroll
        for (int i = 0; i < 2; ++i) {
            int slot = i * 256 + tid;           // 0..511
            int row  = slot >> 3;               // 0..63
            int g    = slot & 7;                // 16B group
            uint32_t soff = (uint32_t)(row * APITCH + g * 16);
            size_t goff = base + (size_t)(k0 + row) * DK + g * 8;
            CPA16(sp + soff,          K + goff);
            CPA16(sp + AV_OFF + soff, V + goff);
        }
        CP_COMMIT();
    };

    // stage Q (fp16, already scaled) + first two K/V tiles
#pragma unroll
    for (int i = 0; i < 4; ++i) {
        int slot = i * 256 + tid;               // 0..1023
        int row  = slot >> 3;                   // 0..127
        int g    = slot & 7;
        uint4 v = *(const uint4*)(Q + base + (size_t)(q0 + row) * DK + g * 8);
        *(uint4*)(smem + QF_OFF + row * APITCH + g * 16) = v;
    }
    issue_kv(0);
    issue_kv(1);
    __syncthreads();

    uint32_t qf[4][4];
    {
        const uint32_t qB = sb + QF_OFF + (uint32_t)(wid * 16) * APITCH + laneOff;
#pragma unroll
        for (int s = 0; s < 4; ++s)
            LDSM_X4(qf[s][0], qf[s][1], qf[s][2], qf[s][3], qB + s * 32);
    }

    float o[8][4];
#pragma unroll
    for (int dt = 0; dt < 8; ++dt)
#pragma unroll
        for (int r = 0; r < 4; ++r) o[dt][r] = 0.0f;
    float mi0 = -1.0e30f, mi1 = -1.0e30f, li0 = 0.0f, li1 = 0.0f;

#pragma unroll 1
    for (int t = 0; t < 32; ++t) {
        if (tid < 64)
            ((int*)(smem + MASK_OFF))[(t & 1) * 64 + tid] = mask[b * S_LEN + t * 64 + tid];
        if (t < 31) CP_WAIT1(); else CP_WAIT0();
        __syncthreads();
        if (t + 2 < 32) issue_kv(t + 2);

        const uint32_t kB = sb + (uint32_t)((t % 3) * KV_STAGE) + laneOff;

        // ---- S = Q K^T ----
        float s_[8][4];
#pragma unroll
        for (int nt = 0; nt < 8; ++nt)
#pragma unroll
            for (int r = 0; r < 4; ++r) s_[nt][r] = 0.0f;
#pragma unroll
        for (int st = 0; st < 4; ++st) {
#pragma unroll
            for (int g2 = 0; g2 < 4; ++g2) {
                uint32_t kf[4];
                LDSM_X4(kf[0], kf[1], kf[2], kf[3],
                        kB + g2 * (16 * APITCH) + st * 32);
                MMA_FP16(s_[2 * g2],     qf[st], kf[0], kf[2]);
                MMA_FP16(s_[2 * g2 + 1], qf[st], kf[1], kf[3]);
            }
        }

        // ---- mask ----
        const int* mbuf = (const int*)(smem + MASK_OFF) + (t & 1) * 64;
#pragma unroll
        for (int nt = 0; nt < 8; ++nt) {
            int2 mv = *(const int2*)&mbuf[nt * 8 + (lane & 3) * 2];
            if (mv.x == 0) { s_[nt][0] = -1.0e9f; s_[nt][2] = -1.0e9f; }
            if (mv.y == 0) { s_[nt][1] = -1.0e9f; s_[nt][3] = -1.0e9f; }
        }

        // ---- online softmax ----
        float mx0 = -1.0e30f, mx1 = -1.0e30f;
#pragma unroll
        for (int nt = 0; nt < 8; ++nt) {
            mx0 = fmaxf(mx0, fmaxf(s_[nt][0], s_[nt][1]));
            mx1 = fmaxf(mx1, fmaxf(s_[nt][2], s_[nt][3]));
        }
        mx0 = fmaxf(mx0, __shfl_xor_sync(0xffffffffu, mx0, 1));
        mx0 = fmaxf(mx0, __shfl_xor_sync(0xffffffffu, mx0, 2));
        mx1 = fmaxf(mx1, __shfl_xor_sync(0xffffffffu, mx1, 1));
        mx1 = fmaxf(mx1, __shfl_xor_sync(0xffffffffu, mx1, 2));
        const float mn0 = fmaxf(mi0, mx0), mn1 = fmaxf(mi1, mx1);
        const float a0 = __expf(mi0 - mn0), a1 = __expf(mi1 - mn1);
        mi0 = mn0; mi1 = mn1;

        float sum0 = 0.0f, sum1 = 0.0f;
#pragma unroll
        for (int nt = 0; nt < 8; ++nt) {
            s_[nt][0] = __expf(s_[nt][0] - mn0);
            s_[nt][1] = __expf(s_[nt][1] - mn0);
            s_[nt][2] = __expf(s_[nt][2] - mn1);
            s_[nt][3] = __expf(s_[nt][3] - mn1);
            sum0 += s_[nt][0] + s_[nt][1];
            sum1 += s_[nt][2] + s_[nt][3];
        }
        sum0 += __shfl_xor_sync(0xffffffffu, sum0, 1);
        sum0 += __shfl_xor_sync(0xffffffffu, sum0, 2);
        sum1 += __shfl_xor_sync(0xffffffffu, sum1, 1);
        sum1 += __shfl_xor_sync(0xffffffffu, sum1, 2);
        li0 = li0 * a0 + sum0;
        li1 = li1 * a1 + sum1;

#pragma unroll
        for (int dt = 0; dt < 8; ++dt) {
            o[dt][0] *= a0; o[dt][1] *= a0;
            o[dt][2] *= a1; o[dt][3] *= a1;
        }

        // ---- O += P V ----
        const uint32_t vB = sb + (uint32_t)((t % 3) * KV_STAGE) + AV_OFF + laneOff;
#pragma unroll
        for (int st = 0; st < 4; ++st) {
            uint32_t pf[4];
            pf[0] = pack_f16(s_[2 * st][0],     s_[2 * st][1]);
            pf[1] = pack_f16(s_[2 * st][2],     s_[2 * st][3]);
            pf[2] = pack_f16(s_[2 * st + 1][0], s_[2 * st + 1][1]);
            pf[3] = pack_f16(s_[2 * st + 1][2], s_[2 * st + 1][3]);
#pragma unroll
            for (int j = 0; j < 4; ++j) {
                uint32_t vf[4];
                LDSM_X4_T(vf[0], vf[1], vf[2], vf[3],
                          vB + st * (16 * APITCH) + j * 32);
                MMA_FP16(o[2 * j],     pf, vf[0], vf[1]);
                MMA_FP16(o[2 * j + 1], pf, vf[2], vf[3]);
            }
        }
    }

    // ---- epilogue: normalize, write ctx fp16 (b, s, h*64+d) ----
    const int g  = lane >> 2;
    const int t2 = (lane & 3) * 2;
    const int row0 = q0 + wid * 16 + g;
    const int row1 = row0 + 8;
    const float inv0 = 1.0f / li0, inv1 = 1.0f / li1;
#pragma unroll
    for (int dt = 0; dt < 8; ++dt) {
        int col = h * DK + dt * 8 + t2;
        *(uint32_t*)(g_ctx + (size_t)(b * S_LEN + row0) * DMODEL + col) =
            pack_f16(o[dt][0] * inv0, o[dt][1] * inv0);
        *(uint32_t*)(g_ctx + (size_t)(b * S_LEN + row1) * DMODEL + col) =
            pack_f16(o[dt][2] * inv1, o[dt][3] * inv1);
    }
}

// ---------------------------------------------------------------------------
extern "C" void kernel_launch(void* const* d_in, const int* in_sizes, int n_in,
                              void* d_out, int out_size)
{
    const float* query = (const float*)d_in[0];
    const float* key   = (const float*)d_in[1];
    const float* value = (const float*)d_in[2];
    const int*   mask  = (const int*)d_in[3];
    const float* Wq = (const float*)d_in[4];
    const float* bq = (const float*)d_in[5];
    const float* Wk = (const float*)d_in[6];
    const float* bk = (const float*)d_in[7];
    const float* Wv = (const float*)d_in[8];
    const float* bv = (const float*)d_in[9];
    const float* Wo = (const float*)d_in[10];
    const float* bo = (const float*)d_in[11];
    float* out = (float*)d_out;

    cudaFuncSetAttribute(gemm_qkv, cudaFuncAttributeMaxDynamicSharedMemorySize, GEMM_SMEM);
    cudaFuncSetAttribute(gemm_out, cudaFuncAttributeMaxDynamicSharedMemorySize, GEMM_SMEM);
    cudaFuncSetAttribute(attn_mma, cudaFuncAttributeMaxDynamicSharedMemorySize, ATTN_SMEM);

    dim3 pg((MTOT * DMODEL / 4 + 255) / 256, 7);     // (4096, 7)
    prep_f16<<<pg, 256>>>(query, key, value, Wq, Wk, Wv, Wo);

    dim3 gq(DMODEL / 128, MTOT / 128, 3);            // (8, 32, 3) = 768 CTAs
    gemm_qkv<<<gq, 256, GEMM_SMEM>>>(bq, bk, bv);

    dim3 ag(S_LEN / 128, NHEADS, BATCH);             // (16, 16, 2) = 512 CTAs
    attn_mma<<<ag, 256, ATTN_SMEM>>>(mask);

    dim3 gg(DMODEL / 128, MTOT / 128);               // (8, 32) = 256 CTAs
    gemm_out<<<gg, 256, GEMM_SMEM>>>(bo, out);
}